// round 6
// baseline (speedup 1.0000x reference)
#include <cuda_runtime.h>
#include <cuda_fp16.h>
#include <cstdint>
#include <math.h>

#define T_STEPS 32
#define BATCH   8192
#define MDIM    4
#define NDIM    2
#define H1      480
#define HID     200
#define H2      320

// ---------------- scratch (device globals; no allocation allowed) -----------
__device__ float g_gx  [BATCH * 3 * HID];
__device__ float g_gh  [BATCH * 3 * HID];
__device__ float g_a2  [BATCH * H2];
__device__ float g_hn  [2 * BATCH * HID];
__device__ float g_prior[BATCH * MDIM];
__device__ float g_post [BATCH * MDIM];
__device__ float g_dm1y [BATCH * NDIM];
__device__ __half g_a1 [BATCH * H1];
__device__ __half g_hnh[BATCH * HID];
__device__ __half g_WgTh[3*HID*H1],  g_WgTl[3*HID*H1];
__device__ __half g_UgTh[3*HID*HID], g_UgTl[3*HID*HID];
__device__ __half g_W2Th[H2*HID],    g_W2Tl[H2*HID];

// ---------------- PTX helpers ------------------------------------------------
__device__ __forceinline__ uint32_t smem_u32(const void* p) {
    uint32_t a;
    asm("{ .reg .u64 t; cvta.to.shared.u64 t, %1; cvt.u32.u64 %0, t; }" : "=r"(a) : "l"(p));
    return a;
}
__device__ __forceinline__ void cp16(uint32_t dst, const void* src) {
    asm volatile("cp.async.cg.shared.global [%0], [%1], 16;" :: "r"(dst), "l"(src) : "memory");
}
__device__ __forceinline__ void sts_zero16(uint32_t addr) {
    asm volatile("st.shared.v4.b32 [%0], {%1,%1,%1,%1};" :: "r"(addr), "r"(0) : "memory");
}
__device__ __forceinline__ void ldsm4(uint32_t* r, uint32_t addr) {
    asm volatile("ldmatrix.sync.aligned.m8n8.x4.shared.b16 {%0,%1,%2,%3}, [%4];"
                 : "=r"(r[0]), "=r"(r[1]), "=r"(r[2]), "=r"(r[3]) : "r"(addr));
}
__device__ __forceinline__ void mma16816(float* c, const uint32_t* a, uint32_t b0, uint32_t b1) {
    asm volatile("mma.sync.aligned.m16n8k16.row.col.f32.f16.f16.f32 "
                 "{%0,%1,%2,%3}, {%4,%5,%6,%7}, {%8,%9}, {%0,%1,%2,%3};"
                 : "+f"(c[0]), "+f"(c[1]), "+f"(c[2]), "+f"(c[3])
                 : "r"(a[0]), "r"(a[1]), "r"(a[2]), "r"(a[3]), "r"(b0), "r"(b1));
}

// ---------------- split-fp16 HMMA GEMM ---------------------------------------
// C[128 x BN] = A[M x K] @ (Bh+Bl)^T[N x K] + bias.  BN = 16*NF.
// BK=32, 256 threads, 8 warps (4m x 2n), warp tile 32 x (8*NF), 2-stage cp.async.
#define ROWB 80                       // 64B data + 16B pad (conflict-free ldmatrix)

template<int NF, bool RELU>
__global__ __launch_bounds__(256)
void gemm_mma(const __half* __restrict__ A,
              const __half* __restrict__ Bh, const __half* __restrict__ Bl,
              const float* __restrict__ bias, float* __restrict__ C,
              int Ncols, int K) {
    constexpr int BN   = 16 * NF;
    constexpr int A_PL = 128 * ROWB;
    constexpr int B_PL = BN * ROWB;
    constexpr int STG  = A_PL + 2 * B_PL;
    extern __shared__ char smem[];
    const uint32_t s0 = smem_u32(smem);
    const int tid  = threadIdx.x;
    const int lane = tid & 31, wid = tid >> 5;
    const int wm = (wid & 3) * 32;
    const int wn = (wid >> 2) * (8 * NF);
    const int bm = blockIdx.y * 128;
    const int bn = blockIdx.x * BN;

    float acc[2][NF][4];
    #pragma unroll
    for (int i = 0; i < 2; i++)
        #pragma unroll
        for (int j = 0; j < NF; j++)
            #pragma unroll
            for (int k = 0; k < 4; k++) acc[i][j][k] = 0.f;

    const int NC = (K + 31) / 32;

    auto load_stage = [&](int s) {
        uint32_t base = s0 + (uint32_t)(s & 1) * STG;
        int k0 = s * 32;
        int kc = K - k0; if (kc > 32) kc = 32;
        #pragma unroll
        for (int it = 0; it < 2; it++) {                 // A: 128 rows x 4 chunks
            int idx = tid + it * 256;
            int r = idx >> 2, ch = idx & 3;
            uint32_t dst = base + (uint32_t)r * ROWB + (uint32_t)ch * 16;
            if (ch * 8 < kc) cp16(dst, A + (size_t)(bm + r) * K + k0 + ch * 8);
            else             sts_zero16(dst);
        }
        #pragma unroll
        for (int it = 0; it < BN / 32; it++) {           // B: 2 planes x BN rows x 4 chunks
            int idx = tid + it * 256;
            int plane = idx / (BN * 4);
            int r = (idx >> 2) & (BN - 1);
            int ch = idx & 3;
            uint32_t dst = base + A_PL + (uint32_t)plane * B_PL
                         + (uint32_t)r * ROWB + (uint32_t)ch * 16;
            if ((bn + r) < Ncols && ch * 8 < kc)
                cp16(dst, (plane ? Bl : Bh) + (size_t)(bn + r) * K + k0 + ch * 8);
            else
                sts_zero16(dst);
        }
        asm volatile("cp.async.commit_group;" ::: "memory");
    };

    load_stage(0);

    const uint32_t a_lrow = (uint32_t)(lane & 15) * ROWB + (uint32_t)(lane >> 4) * 16;
    const uint32_t b_lrow = (uint32_t)((lane & 7) + ((lane >> 3) & 1) * 8) * ROWB
                          + (uint32_t)(lane >> 4) * 16;

    for (int i = 0; i < NC; i++) {
        if (i + 1 < NC) {
            load_stage(i + 1);
            asm volatile("cp.async.wait_group 1;" ::: "memory");
        } else {
            asm volatile("cp.async.wait_group 0;" ::: "memory");
        }
        __syncthreads();

        uint32_t base = s0 + (uint32_t)(i & 1) * STG;
        uint32_t sA = base, sB = base + A_PL;

        #pragma unroll
        for (int ks = 0; ks < 2; ks++) {
            uint32_t koff = (uint32_t)ks * 32;           // 16 halves = 32B
            uint32_t a[2][4];
            #pragma unroll
            for (int fm = 0; fm < 2; fm++)
                ldsm4(a[fm], sA + (uint32_t)(wm + fm * 16) * ROWB + koff + a_lrow);
            #pragma unroll
            for (int plane = 0; plane < 2; plane++) {
                uint32_t bf[NF / 2][4];
                #pragma unroll
                for (int nb = 0; nb < NF / 2; nb++)
                    ldsm4(bf[nb], sB + (uint32_t)plane * B_PL
                                  + (uint32_t)(wn + nb * 16) * ROWB + koff + b_lrow);
                #pragma unroll
                for (int fm = 0; fm < 2; fm++)
                    #pragma unroll
                    for (int j = 0; j < NF; j++)
                        mma16816(acc[fm][j], a[fm], bf[j >> 1][j & 1], bf[j >> 1][(j & 1) + 2]);
            }
        }
        __syncthreads();
    }

    const int qid = lane >> 2, qt = lane & 3;
    #pragma unroll
    for (int fm = 0; fm < 2; fm++) {
        int row = bm + wm + fm * 16 + qid;
        #pragma unroll
        for (int j = 0; j < NF; j++) {
            int col = bn + wn + j * 8 + qt * 2;
            if (col >= Ncols) continue;
            float b0 = __ldg(&bias[col]), b1 = __ldg(&bias[col + 1]);
            float2 v0 = make_float2(acc[fm][j][0] + b0, acc[fm][j][1] + b1);
            float2 v1 = make_float2(acc[fm][j][2] + b0, acc[fm][j][3] + b1);
            if (RELU) {
                v0.x = fmaxf(v0.x, 0.f); v0.y = fmaxf(v0.y, 0.f);
                v1.x = fmaxf(v1.x, 0.f); v1.y = fmaxf(v1.y, 0.f);
            }
            *(float2*)&C[(size_t)row * Ncols + col]       = v0;
            *(float2*)&C[(size_t)(row + 8) * Ncols + col] = v1;
        }
    }
}

// ---------------- small kernels ---------------------------------------------
__device__ __forceinline__ void wsplit_store(float v, __half* hi, __half* lo, size_t idx) {
    __half h = __float2half_rn(v);
    hi[idx] = h;
    lo[idx] = __float2half_rn(v - __half2float(h));
}

__global__ void init_kernel(const float* __restrict__ hn0, float* __restrict__ hn,
                            __half* __restrict__ hnh,
                            float* __restrict__ prior, float* __restrict__ post) {
    int i = blockIdx.x * blockDim.x + threadIdx.x;
    if (i < BATCH * HID) {
        float v = hn0[i];
        hn[i] = v;
        hnh[i] = __float2half_rn(v);
    }
    if (i < BATCH * MDIM) { prior[i] = 0.f; post[i] = 0.f; }
}

__global__ void wsplit_kernel(const float* __restrict__ in,
                              __half* __restrict__ oh, __half* __restrict__ ol,
                              int K, int N) {
    int i = blockIdx.x * blockDim.x + threadIdx.x;
    if (i < K * N) {
        int k = i / N, n = i % N;
        wsplit_store(in[i], oh, ol, (size_t)n * K + k);
    }
}

// features + a1 for 64 batch rows per block (also standalone for t=0)
__device__ __forceinline__ void feat_a1_body(
        const float* __restrict__ y_t,
        const float* __restrict__ F, const float* __restrict__ Hm,
        const float* __restrict__ W1, const float* __restrict__ b1,
        const float* __restrict__ post, float* __restrict__ prior,
        float* __restrict__ dm1y_out, __half* __restrict__ a1,
        float (*feat)[9], int tid, int b0) {
    if (tid < 64) {
        int b = b0 + tid;
        float p[4], pr_old[4];
        #pragma unroll
        for (int m = 0; m < 4; m++) { p[m] = post[b*4+m]; pr_old[m] = prior[b*4+m]; }
        float pn[4];
        #pragma unroll
        for (int i = 0; i < 4; i++) {
            float s = 0.f;
            #pragma unroll
            for (int j = 0; j < 4; j++) s += __ldg(&F[i*4+j]) * p[j];
            pn[i] = s;
        }
        float my[2];
        #pragma unroll
        for (int i = 0; i < 2; i++) {
            float s = 0.f;
            #pragma unroll
            for (int j = 0; j < 4; j++) s += __ldg(&Hm[i*4+j]) * pn[j];
            my[i] = s;
        }
        float dy0 = y_t[b*2+0] - my[0];
        float dy1 = y_t[b*2+1] - my[1];
        dm1y_out[b*2+0] = dy0;
        dm1y_out[b*2+1] = dy1;
        float inv_y = rsqrtf(fmaxf(dy0*dy0 + dy1*dy1, 1e-12f));
        feat[tid][0] = dy0*inv_y; feat[tid][1] = dy1*inv_y;
        feat[tid][2] = dy0*inv_y; feat[tid][3] = dy1*inv_y;
        float d[4], s2 = 0.f;
        #pragma unroll
        for (int m = 0; m < 4; m++) { d[m] = p[m] - pr_old[m]; s2 += d[m]*d[m]; }
        float inv_x = rsqrtf(fmaxf(s2, 1e-12f));
        #pragma unroll
        for (int m = 0; m < 4; m++) feat[tid][4+m] = d[m]*inv_x;
        #pragma unroll
        for (int m = 0; m < 4; m++) prior[b*4+m] = pn[m];
    }
    __syncthreads();
    for (int idx = tid; idx < 64 * H1; idx += 256) {
        int r = idx / H1, c = idx % H1;
        float s = __ldg(&b1[c]);
        #pragma unroll
        for (int k = 0; k < 8; k++) s += feat[r][k] * __ldg(&W1[k*H1 + c]);
        a1[(size_t)(b0 + r) * H1 + c] = __float2half_rn(fmaxf(s, 0.f));
    }
}

__global__ void feat_a1_kernel(const float* __restrict__ y_t,
                               const float* __restrict__ F, const float* __restrict__ Hm,
                               const float* __restrict__ W1, const float* __restrict__ b1,
                               const float* __restrict__ post, float* __restrict__ prior,
                               float* __restrict__ dm1y_out, __half* __restrict__ a1) {
    __shared__ float feat[64][9];
    feat_a1_body(y_t, F, Hm, W1, b1, post, prior, dm1y_out, a1,
                 feat, threadIdx.x, blockIdx.x * 64);
}

// posterior(t) + features/a1(t+1) fused; 64 batch rows per block.
__global__ void post_feat_kernel(const float* __restrict__ a2, const float* __restrict__ W3,
                                 const float* __restrict__ b3,
                                 const float* __restrict__ y_next,
                                 const float* __restrict__ F, const float* __restrict__ Hm,
                                 const float* __restrict__ W1, const float* __restrict__ b1,
                                 float* __restrict__ prior, float* __restrict__ post,
                                 float* __restrict__ dm1y, float* __restrict__ out_t,
                                 __half* __restrict__ a1) {
    __shared__ float feat[64][9];
    int tid = threadIdx.x;
    int b0 = blockIdx.x * 64;
    // ---- phase 1: posterior, 4-thread teams per row ----
    {
        int r = tid >> 2, lane4 = tid & 3;
        int b = b0 + r;
        float kg[8];
        #pragma unroll
        for (int o = 0; o < 8; o++) kg[o] = 0.f;
        const float* arow = a2 + (size_t)b * H2;
        for (int k = lane4; k < H2; k += 4) {
            float a = arow[k];
            float4 w0 = *(const float4*)(W3 + k*8);
            float4 w1 = *(const float4*)(W3 + k*8 + 4);
            kg[0] = fmaf(a, w0.x, kg[0]); kg[1] = fmaf(a, w0.y, kg[1]);
            kg[2] = fmaf(a, w0.z, kg[2]); kg[3] = fmaf(a, w0.w, kg[3]);
            kg[4] = fmaf(a, w1.x, kg[4]); kg[5] = fmaf(a, w1.y, kg[5]);
            kg[6] = fmaf(a, w1.z, kg[6]); kg[7] = fmaf(a, w1.w, kg[7]);
        }
        #pragma unroll
        for (int off = 2; off > 0; off >>= 1)
            #pragma unroll
            for (int o = 0; o < 8; o++)
                kg[o] += __shfl_down_sync(0xFFFFFFFFu, kg[o], off, 4);
        if (lane4 == 0) {
            float dy0 = dm1y[b*2+0], dy1 = dm1y[b*2+1];
            #pragma unroll
            for (int m = 0; m < 4; m++) {
                float k0 = kg[2*m]   + __ldg(&b3[2*m]);
                float k1 = kg[2*m+1] + __ldg(&b3[2*m+1]);
                float pv = prior[b*4+m] + k0*dy0 + k1*dy1;
                post[b*4+m]  = pv;
                out_t[b*4+m] = pv;
            }
        }
    }
    __syncthreads();
    // ---- phase 2: features + a1 for next step ----
    feat_a1_body(y_next, F, Hm, W1, b1, post, prior, dm1y, a1, feat, tid, b0);
}

__global__ void gru_gate_kernel(const float* __restrict__ Gx, const float* __restrict__ Gh,
                                const float* __restrict__ h_in, float* __restrict__ h_out,
                                __half* __restrict__ hnh) {
    int idx = blockIdx.x * blockDim.x + threadIdx.x;
    if (idx >= BATCH * HID) return;
    int b = idx / HID, j = idx % HID;
    const float* gx = Gx + (size_t)b * 3 * HID;
    const float* gh = Gh + (size_t)b * 3 * HID;
    float z = 1.f / (1.f + __expf(-(gx[j]       + gh[j])));
    float r = 1.f / (1.f + __expf(-(gx[j + HID] + gh[j + HID])));
    float hc = tanhf(gx[j + 2*HID] + r * gh[j + 2*HID]);
    float h = h_in[idx];
    float v = z * h + (1.f - z) * hc;
    h_out[idx] = v;
    hnh[idx] = __float2half_rn(v);
}

__global__ void out_kernel(const float* __restrict__ a2, const float* __restrict__ W3,
                           const float* __restrict__ b3, const float* __restrict__ dm1y,
                           const float* __restrict__ prior, float* __restrict__ post,
                           float* __restrict__ out_t) {
    int tid = threadIdx.x;
    int lane = tid & 7;
    int b = blockIdx.x * 32 + (tid >> 3);
    float kg[8];
    #pragma unroll
    for (int o = 0; o < 8; o++) kg[o] = 0.f;
    const float* arow = a2 + (size_t)b * H2;
    for (int k = lane; k < H2; k += 8) {
        float a = arow[k];
        float4 w0 = *(const float4*)(W3 + k*8);
        float4 w1 = *(const float4*)(W3 + k*8 + 4);
        kg[0] = fmaf(a, w0.x, kg[0]); kg[1] = fmaf(a, w0.y, kg[1]);
        kg[2] = fmaf(a, w0.z, kg[2]); kg[3] = fmaf(a, w0.w, kg[3]);
        kg[4] = fmaf(a, w1.x, kg[4]); kg[5] = fmaf(a, w1.y, kg[5]);
        kg[6] = fmaf(a, w1.z, kg[6]); kg[7] = fmaf(a, w1.w, kg[7]);
    }
    #pragma unroll
    for (int off = 4; off > 0; off >>= 1)
        #pragma unroll
        for (int o = 0; o < 8; o++)
            kg[o] += __shfl_down_sync(0xFFFFFFFFu, kg[o], off, 8);
    if (lane == 0) {
        float dy0 = dm1y[b*2+0], dy1 = dm1y[b*2+1];
        #pragma unroll
        for (int m = 0; m < 4; m++) {
            float k0 = kg[2*m]   + __ldg(&b3[2*m]);
            float k1 = kg[2*m+1] + __ldg(&b3[2*m+1]);
            float pv = prior[b*4+m] + k0*dy0 + k1*dy1;
            post[b*4+m] = pv;
            out_t[b*4+m] = pv;
        }
    }
}

// ---------------- launch ----------------------------------------------------
extern "C" void kernel_launch(void* const* d_in, const int* in_sizes, int n_in,
                              void* d_out, int out_size) {
    const float* y   = (const float*)d_in[0];
    const float* F   = (const float*)d_in[1];
    const float* Hm  = (const float*)d_in[2];
    const float* W1  = (const float*)d_in[3];
    const float* b1  = (const float*)d_in[4];
    const float* Wg  = (const float*)d_in[5];   // [480,600]
    const float* Ug  = (const float*)d_in[6];   // [200,600]
    const float* bg  = (const float*)d_in[7];   // [2,600]
    const float* W2  = (const float*)d_in[8];   // [200,320]
    const float* b2  = (const float*)d_in[9];
    const float* W3  = (const float*)d_in[10];
    const float* b3  = (const float*)d_in[11];
    const float* hn0 = (const float*)d_in[12];
    float* out = (float*)d_out;

    float *gx, *gh, *a2, *hn, *prior, *post, *dm1y;
    __half *a1, *hnh, *WgTh, *WgTl, *UgTh, *UgTl, *W2Th, *W2Tl;
    cudaGetSymbolAddress((void**)&gx,   g_gx);
    cudaGetSymbolAddress((void**)&gh,   g_gh);
    cudaGetSymbolAddress((void**)&a2,   g_a2);
    cudaGetSymbolAddress((void**)&hn,   g_hn);
    cudaGetSymbolAddress((void**)&prior,g_prior);
    cudaGetSymbolAddress((void**)&post, g_post);
    cudaGetSymbolAddress((void**)&dm1y, g_dm1y);
    cudaGetSymbolAddress((void**)&a1,   g_a1);
    cudaGetSymbolAddress((void**)&hnh,  g_hnh);
    cudaGetSymbolAddress((void**)&WgTh, g_WgTh);
    cudaGetSymbolAddress((void**)&WgTl, g_WgTl);
    cudaGetSymbolAddress((void**)&UgTh, g_UgTh);
    cudaGetSymbolAddress((void**)&UgTl, g_UgTl);
    cudaGetSymbolAddress((void**)&W2Th, g_W2Th);
    cudaGetSymbolAddress((void**)&W2Tl, g_W2Tl);

    // smem: NF=8 stage = 128*80 + 2*128*80 = 30720; x2 = 61440
    //       NF=4 stage = 128*80 + 2*64*80  = 20480; x2 = 40960
    const int SMEM8 = 2 * (128 * ROWB + 2 * 128 * ROWB);
    const int SMEM4 = 2 * (128 * ROWB + 2 * 64 * ROWB);
    cudaFuncSetAttribute(gemm_mma<8, false>,
                         cudaFuncAttributeMaxDynamicSharedMemorySize, SMEM8);
    cudaFuncSetAttribute(gemm_mma<4, true>,
                         cudaFuncAttributeMaxDynamicSharedMemorySize, SMEM4);

    wsplit_kernel<<<(H1*3*HID + 255)/256, 256>>>(Wg, WgTh, WgTl, H1, 3*HID);
    wsplit_kernel<<<(HID*3*HID + 255)/256, 256>>>(Ug, UgTh, UgTl, HID, 3*HID);
    wsplit_kernel<<<(HID*H2 + 255)/256, 256>>>(W2, W2Th, W2Tl, HID, H2);
    init_kernel<<<(BATCH*HID + 255)/256, 256>>>(hn0, hn, hnh, prior, post);

    feat_a1_kernel<<<BATCH/64, 256>>>(y, F, Hm, W1, b1, post, prior, dm1y, a1);

    for (int t = 0; t < T_STEPS; t++) {
        const float* hin = hn + (size_t)(t & 1) * BATCH * HID;
        float* hout      = hn + (size_t)((t + 1) & 1) * BATCH * HID;

        gemm_mma<8, false><<<dim3(5, BATCH/128), 256, SMEM8>>>(
            a1, WgTh, WgTl, bg,          gx, 3*HID, H1);
        gemm_mma<8, false><<<dim3(5, BATCH/128), 256, SMEM8>>>(
            hnh, UgTh, UgTl, bg + 3*HID, gh, 3*HID, HID);

        gru_gate_kernel<<<(BATCH*HID + 255)/256, 256>>>(gx, gh, hin, hout, hnh);

        gemm_mma<4, true><<<dim3(5, BATCH/128), 256, SMEM4>>>(
            hnh, W2Th, W2Tl, b2, a2, H2, HID);

        if (t + 1 < T_STEPS) {
            post_feat_kernel<<<BATCH/64, 256>>>(a2, W3, b3,
                y + (size_t)(t + 1) * BATCH * NDIM, F, Hm, W1, b1,
                prior, post, dm1y, out + (size_t)t * BATCH * MDIM, a1);
        } else {
            out_kernel<<<BATCH/32, 256>>>(a2, W3, b3, dm1y, prior, post,
                                          out + (size_t)t * BATCH * MDIM);
        }
    }
}

// round 7
// speedup vs baseline: 1.0837x; 1.0837x over previous
#include <cuda_runtime.h>
#include <cuda_fp16.h>
#include <cstdint>
#include <math.h>

#define T_STEPS 32
#define BATCH   8192
#define MDIM    4
#define NDIM    2
#define H1      480
#define HID     200
#define H2      320

// ---------------- scratch (device globals; no allocation allowed) -----------
__device__ float g_gx  [BATCH * 3 * HID];
__device__ float g_gh  [BATCH * 3 * HID];
__device__ float g_a2  [BATCH * H2];
__device__ float g_hn  [2 * BATCH * HID];
__device__ float g_prior[BATCH * MDIM];
__device__ float g_post [BATCH * MDIM];
__device__ float g_dm1y [BATCH * NDIM];
__device__ __half g_a1 [BATCH * H1];
__device__ __half g_hnh[BATCH * HID];
__device__ __half g_WgTh[3*HID*H1],  g_WgTl[3*HID*H1];
__device__ __half g_UgTh[3*HID*HID], g_UgTl[3*HID*HID];
__device__ __half g_W2Th[H2*HID],    g_W2Tl[H2*HID];

// ---------------- PTX helpers ------------------------------------------------
__device__ __forceinline__ uint32_t smem_u32(const void* p) {
    uint32_t a;
    asm("{ .reg .u64 t; cvta.to.shared.u64 t, %1; cvt.u32.u64 %0, t; }" : "=r"(a) : "l"(p));
    return a;
}
__device__ __forceinline__ void cp16(uint32_t dst, const void* src) {
    asm volatile("cp.async.cg.shared.global [%0], [%1], 16;" :: "r"(dst), "l"(src) : "memory");
}
__device__ __forceinline__ void sts_zero16(uint32_t addr) {
    asm volatile("st.shared.v4.b32 [%0], {%1,%1,%1,%1};" :: "r"(addr), "r"(0) : "memory");
}
__device__ __forceinline__ void ldsm4(uint32_t* r, uint32_t addr) {
    asm volatile("ldmatrix.sync.aligned.m8n8.x4.shared.b16 {%0,%1,%2,%3}, [%4];"
                 : "=r"(r[0]), "=r"(r[1]), "=r"(r[2]), "=r"(r[3]) : "r"(addr));
}
__device__ __forceinline__ void mma16816(float* c, const uint32_t* a, uint32_t b0, uint32_t b1) {
    asm volatile("mma.sync.aligned.m16n8k16.row.col.f32.f16.f16.f32 "
                 "{%0,%1,%2,%3}, {%4,%5,%6,%7}, {%8,%9}, {%0,%1,%2,%3};"
                 : "+f"(c[0]), "+f"(c[1]), "+f"(c[2]), "+f"(c[3])
                 : "r"(a[0]), "r"(a[1]), "r"(a[2]), "r"(a[3]), "r"(b0), "r"(b1));
}

// ---------------- split-fp16 HMMA GEMM (R5 proven config) --------------------
// C[128 x 64 tile] = A[M x K] @ (Bh+Bl)^T[N x K] + bias, fp32 out.
// A single fp16 plane; B hi+lo fp16 planes -> 2 MMA per K16.
// BK=64, 256 threads, 8 warps (4m x 2n), warp tile 32x32, 2-stage cp.async.
#define ROWB   144                    // 128B data + 16B pad (conflict-free ldmatrix)
#define A_PL   (128 * ROWB)           // 18432
#define B_PL   (64 * ROWB)            // 9216
#define STAGE  (A_PL + 2 * B_PL)      // 36864

template<bool RELU>
__global__ __launch_bounds__(256, 2)
void gemm_mma(const __half* __restrict__ A,
              const __half* __restrict__ Bh, const __half* __restrict__ Bl,
              const float* __restrict__ bias, float* __restrict__ C,
              int Ncols, int K) {
    extern __shared__ char smem[];
    const uint32_t s0 = smem_u32(smem);
    const int tid  = threadIdx.x;
    const int lane = tid & 31, wid = tid >> 5;
    const int wm = (wid & 3) * 32;
    const int wn = (wid >> 2) * 32;
    const int bm = blockIdx.y * 128;
    const int bn = blockIdx.x * 64;

    float acc[2][4][4];
    #pragma unroll
    for (int i = 0; i < 2; i++)
        #pragma unroll
        for (int j = 0; j < 4; j++)
            #pragma unroll
            for (int k = 0; k < 4; k++) acc[i][j][k] = 0.f;

    const int NC = (K + 63) / 64;

    auto load_stage = [&](int s) {
        uint32_t base = s0 + (uint32_t)(s & 1) * STAGE;
        int k0 = s * 64;
        int kc = K - k0; if (kc > 64) kc = 64;
        #pragma unroll
        for (int it = 0; it < 4; it++) {             // A: 128 rows x 8 chunks
            int idx = tid + it * 256;
            int r = idx >> 3, ch = idx & 7;
            uint32_t dst = base + (uint32_t)r * ROWB + (uint32_t)ch * 16;
            if (ch * 8 < kc)
                cp16(dst, A + (size_t)(bm + r) * K + k0 + ch * 8);
            else
                sts_zero16(dst);
        }
        #pragma unroll
        for (int it = 0; it < 4; it++) {             // B: 2 planes x 64 rows x 8 chunks
            int idx = tid + it * 256;
            int plane = idx >> 9, r = (idx >> 3) & 63, ch = idx & 7;
            uint32_t dst = base + A_PL + (uint32_t)plane * B_PL
                         + (uint32_t)r * ROWB + (uint32_t)ch * 16;
            if ((bn + r) < Ncols && ch * 8 < kc)
                cp16(dst, (plane ? Bl : Bh) + (size_t)(bn + r) * K + k0 + ch * 8);
            else
                sts_zero16(dst);
        }
        asm volatile("cp.async.commit_group;" ::: "memory");
    };

    load_stage(0);

    const uint32_t a_lrow = (uint32_t)(lane & 15) * ROWB + (uint32_t)(lane >> 4) * 16;
    const uint32_t b_lrow = (uint32_t)((lane & 7) + ((lane >> 3) & 1) * 8) * ROWB
                          + (uint32_t)(lane >> 4) * 16;

    for (int i = 0; i < NC; i++) {
        if (i + 1 < NC) {
            load_stage(i + 1);
            asm volatile("cp.async.wait_group 1;" ::: "memory");
        } else {
            asm volatile("cp.async.wait_group 0;" ::: "memory");
        }
        __syncthreads();

        uint32_t base = s0 + (uint32_t)(i & 1) * STAGE;
        uint32_t sA  = base;
        uint32_t sBh = base + A_PL, sBl = sBh + B_PL;

        #pragma unroll
        for (int ks = 0; ks < 4; ks++) {
            uint32_t koff = (uint32_t)ks * 32;       // 16 halves = 32B
            uint32_t a[2][4], bh[2][4], bl[2][4];
            #pragma unroll
            for (int fm = 0; fm < 2; fm++)
                ldsm4(a[fm], sA + (uint32_t)(wm + fm * 16) * ROWB + koff + a_lrow);
            #pragma unroll
            for (int np = 0; np < 2; np++) {
                uint32_t ro = (uint32_t)(wn + np * 16) * ROWB + koff + b_lrow;
                ldsm4(bh[np], sBh + ro);
                ldsm4(bl[np], sBl + ro);
            }
            #pragma unroll
            for (int fm = 0; fm < 2; fm++)
                #pragma unroll
                for (int j = 0; j < 4; j++) {
                    int np = j >> 1, sel = j & 1;
                    mma16816(acc[fm][j], a[fm], bh[np][sel], bh[np][sel + 2]);
                    mma16816(acc[fm][j], a[fm], bl[np][sel], bl[np][sel + 2]);
                }
        }
        __syncthreads();
    }

    const int qid = lane >> 2, qt = lane & 3;
    #pragma unroll
    for (int fm = 0; fm < 2; fm++) {
        int row = bm + wm + fm * 16 + qid;
        #pragma unroll
        for (int j = 0; j < 4; j++) {
            int col = bn + wn + j * 8 + qt * 2;
            if (col >= Ncols) continue;
            float b0 = __ldg(&bias[col]), b1 = __ldg(&bias[col + 1]);
            float2 v0 = make_float2(acc[fm][j][0] + b0, acc[fm][j][1] + b1);
            float2 v1 = make_float2(acc[fm][j][2] + b0, acc[fm][j][3] + b1);
            if (RELU) {
                v0.x = fmaxf(v0.x, 0.f); v0.y = fmaxf(v0.y, 0.f);
                v1.x = fmaxf(v1.x, 0.f); v1.y = fmaxf(v1.y, 0.f);
            }
            *(float2*)&C[(size_t)row * Ncols + col]       = v0;
            *(float2*)&C[(size_t)(row + 8) * Ncols + col] = v1;
        }
    }
}

// ---------------- small kernels ---------------------------------------------
__device__ __forceinline__ void wsplit_store(float v, __half* hi, __half* lo, size_t idx) {
    __half h = __float2half_rn(v);
    hi[idx] = h;
    lo[idx] = __float2half_rn(v - __half2float(h));
}

__global__ void init_kernel(const float* __restrict__ hn0, float* __restrict__ hn,
                            __half* __restrict__ hnh,
                            float* __restrict__ prior, float* __restrict__ post) {
    int i = blockIdx.x * blockDim.x + threadIdx.x;
    if (i < BATCH * HID) {
        float v = hn0[i];
        hn[i] = v;
        hnh[i] = __float2half_rn(v);
    }
    if (i < BATCH * MDIM) { prior[i] = 0.f; post[i] = 0.f; }
}

__global__ void wsplit_kernel(const float* __restrict__ in,
                              __half* __restrict__ oh, __half* __restrict__ ol,
                              int K, int N) {
    int i = blockIdx.x * blockDim.x + threadIdx.x;
    if (i < K * N) {
        int k = i / N, n = i % N;
        wsplit_store(in[i], oh, ol, (size_t)n * K + k);
    }
}

// features + a1 for 64 batch rows per block
__device__ __forceinline__ void feat_a1_body(
        const float* __restrict__ y_t,
        const float* __restrict__ F, const float* __restrict__ Hm,
        const float* __restrict__ W1, const float* __restrict__ b1,
        const float* __restrict__ post, float* __restrict__ prior,
        float* __restrict__ dm1y_out, __half* __restrict__ a1,
        float (*feat)[9], int tid, int b0) {
    if (tid < 64) {
        int b = b0 + tid;
        float p[4], pr_old[4];
        #pragma unroll
        for (int m = 0; m < 4; m++) { p[m] = post[b*4+m]; pr_old[m] = prior[b*4+m]; }
        float pn[4];
        #pragma unroll
        for (int i = 0; i < 4; i++) {
            float s = 0.f;
            #pragma unroll
            for (int j = 0; j < 4; j++) s += __ldg(&F[i*4+j]) * p[j];
            pn[i] = s;
        }
        float my[2];
        #pragma unroll
        for (int i = 0; i < 2; i++) {
            float s = 0.f;
            #pragma unroll
            for (int j = 0; j < 4; j++) s += __ldg(&Hm[i*4+j]) * pn[j];
            my[i] = s;
        }
        float dy0 = y_t[b*2+0] - my[0];
        float dy1 = y_t[b*2+1] - my[1];
        dm1y_out[b*2+0] = dy0;
        dm1y_out[b*2+1] = dy1;
        float inv_y = rsqrtf(fmaxf(dy0*dy0 + dy1*dy1, 1e-12f));
        feat[tid][0] = dy0*inv_y; feat[tid][1] = dy1*inv_y;
        feat[tid][2] = dy0*inv_y; feat[tid][3] = dy1*inv_y;
        float d[4], s2 = 0.f;
        #pragma unroll
        for (int m = 0; m < 4; m++) { d[m] = p[m] - pr_old[m]; s2 += d[m]*d[m]; }
        float inv_x = rsqrtf(fmaxf(s2, 1e-12f));
        #pragma unroll
        for (int m = 0; m < 4; m++) feat[tid][4+m] = d[m]*inv_x;
        #pragma unroll
        for (int m = 0; m < 4; m++) prior[b*4+m] = pn[m];
    }
    __syncthreads();
    for (int idx = tid; idx < 64 * H1; idx += 256) {
        int r = idx / H1, c = idx % H1;
        float s = __ldg(&b1[c]);
        #pragma unroll
        for (int k = 0; k < 8; k++) s += feat[r][k] * __ldg(&W1[k*H1 + c]);
        a1[(size_t)(b0 + r) * H1 + c] = __float2half_rn(fmaxf(s, 0.f));
    }
}

__global__ void feat_a1_kernel(const float* __restrict__ y_t,
                               const float* __restrict__ F, const float* __restrict__ Hm,
                               const float* __restrict__ W1, const float* __restrict__ b1,
                               const float* __restrict__ post, float* __restrict__ prior,
                               float* __restrict__ dm1y_out, __half* __restrict__ a1) {
    __shared__ float feat[64][9];
    feat_a1_body(y_t, F, Hm, W1, b1, post, prior, dm1y_out, a1,
                 feat, threadIdx.x, blockIdx.x * 64);
}

// posterior(t) + features/a1(t+1) fused; 64 batch rows per block.
__global__ void post_feat_kernel(const float* __restrict__ a2, const float* __restrict__ W3,
                                 const float* __restrict__ b3,
                                 const float* __restrict__ y_next,
                                 const float* __restrict__ F, const float* __restrict__ Hm,
                                 const float* __restrict__ W1, const float* __restrict__ b1,
                                 float* __restrict__ prior, float* __restrict__ post,
                                 float* __restrict__ dm1y, float* __restrict__ out_t,
                                 __half* __restrict__ a1) {
    __shared__ float feat[64][9];
    int tid = threadIdx.x;
    int b0 = blockIdx.x * 64;
    // ---- phase 1: posterior, 4-thread teams per row ----
    {
        int r = tid >> 2, lane4 = tid & 3;
        int b = b0 + r;
        float kg[8];
        #pragma unroll
        for (int o = 0; o < 8; o++) kg[o] = 0.f;
        const float* arow = a2 + (size_t)b * H2;
        for (int k = lane4; k < H2; k += 4) {
            float a = arow[k];
            float4 w0 = *(const float4*)(W3 + k*8);
            float4 w1 = *(const float4*)(W3 + k*8 + 4);
            kg[0] = fmaf(a, w0.x, kg[0]); kg[1] = fmaf(a, w0.y, kg[1]);
            kg[2] = fmaf(a, w0.z, kg[2]); kg[3] = fmaf(a, w0.w, kg[3]);
            kg[4] = fmaf(a, w1.x, kg[4]); kg[5] = fmaf(a, w1.y, kg[5]);
            kg[6] = fmaf(a, w1.z, kg[6]); kg[7] = fmaf(a, w1.w, kg[7]);
        }
        #pragma unroll
        for (int off = 2; off > 0; off >>= 1)
            #pragma unroll
            for (int o = 0; o < 8; o++)
                kg[o] += __shfl_down_sync(0xFFFFFFFFu, kg[o], off, 4);
        if (lane4 == 0) {
            float dy0 = dm1y[b*2+0], dy1 = dm1y[b*2+1];
            #pragma unroll
            for (int m = 0; m < 4; m++) {
                float k0 = kg[2*m]   + __ldg(&b3[2*m]);
                float k1 = kg[2*m+1] + __ldg(&b3[2*m+1]);
                float pv = prior[b*4+m] + k0*dy0 + k1*dy1;
                post[b*4+m]  = pv;
                out_t[b*4+m] = pv;
            }
        }
    }
    __syncthreads();
    // ---- phase 2: features + a1 for next step ----
    feat_a1_body(y_next, F, Hm, W1, b1, post, prior, dm1y, a1, feat, tid, b0);
}

// GRU gate combine, float2-vectorized (HID=200 -> 100 pairs per row)
__global__ void gru_gate_kernel(const float* __restrict__ Gx, const float* __restrict__ Gh,
                                const float* __restrict__ h_in, float* __restrict__ h_out,
                                __half* __restrict__ hnh) {
    int idx = blockIdx.x * blockDim.x + threadIdx.x;     // pair index
    if (idx >= BATCH * HID / 2) return;
    int b = idx / (HID / 2), jp = idx % (HID / 2);
    const float* gx = Gx + (size_t)b * 3 * HID;
    const float* gh = Gh + (size_t)b * 3 * HID;
    int j = jp * 2;
    float2 xz = *(const float2*)&gx[j];
    float2 hz = *(const float2*)&gh[j];
    float2 xr = *(const float2*)&gx[j + HID];
    float2 hr = *(const float2*)&gh[j + HID];
    float2 xh = *(const float2*)&gx[j + 2*HID];
    float2 hh = *(const float2*)&gh[j + 2*HID];
    float2 h  = *(const float2*)&h_in[(size_t)b * HID + j];
    float z0 = 1.f / (1.f + __expf(-(xz.x + hz.x)));
    float z1 = 1.f / (1.f + __expf(-(xz.y + hz.y)));
    float r0 = 1.f / (1.f + __expf(-(xr.x + hr.x)));
    float r1 = 1.f / (1.f + __expf(-(xr.y + hr.y)));
    float c0 = tanhf(xh.x + r0 * hh.x);
    float c1 = tanhf(xh.y + r1 * hh.y);
    float v0 = z0 * h.x + (1.f - z0) * c0;
    float v1 = z1 * h.y + (1.f - z1) * c1;
    *(float2*)&h_out[(size_t)b * HID + j] = make_float2(v0, v1);
    __half2 hv; hv.x = __float2half_rn(v0); hv.y = __float2half_rn(v1);
    *(__half2*)&hnh[(size_t)b * HID + j] = hv;
}

__global__ void out_kernel(const float* __restrict__ a2, const float* __restrict__ W3,
                           const float* __restrict__ b3, const float* __restrict__ dm1y,
                           const float* __restrict__ prior, float* __restrict__ post,
                           float* __restrict__ out_t) {
    int tid = threadIdx.x;
    int lane = tid & 7;
    int b = blockIdx.x * 32 + (tid >> 3);
    float kg[8];
    #pragma unroll
    for (int o = 0; o < 8; o++) kg[o] = 0.f;
    const float* arow = a2 + (size_t)b * H2;
    for (int k = lane; k < H2; k += 8) {
        float a = arow[k];
        float4 w0 = *(const float4*)(W3 + k*8);
        float4 w1 = *(const float4*)(W3 + k*8 + 4);
        kg[0] = fmaf(a, w0.x, kg[0]); kg[1] = fmaf(a, w0.y, kg[1]);
        kg[2] = fmaf(a, w0.z, kg[2]); kg[3] = fmaf(a, w0.w, kg[3]);
        kg[4] = fmaf(a, w1.x, kg[4]); kg[5] = fmaf(a, w1.y, kg[5]);
        kg[6] = fmaf(a, w1.z, kg[6]); kg[7] = fmaf(a, w1.w, kg[7]);
    }
    #pragma unroll
    for (int off = 4; off > 0; off >>= 1)
        #pragma unroll
        for (int o = 0; o < 8; o++)
            kg[o] += __shfl_down_sync(0xFFFFFFFFu, kg[o], off, 8);
    if (lane == 0) {
        float dy0 = dm1y[b*2+0], dy1 = dm1y[b*2+1];
        #pragma unroll
        for (int m = 0; m < 4; m++) {
            float k0 = kg[2*m]   + __ldg(&b3[2*m]);
            float k1 = kg[2*m+1] + __ldg(&b3[2*m+1]);
            float pv = prior[b*4+m] + k0*dy0 + k1*dy1;
            post[b*4+m] = pv;
            out_t[b*4+m] = pv;
        }
    }
}

// ---------------- launch ----------------------------------------------------
extern "C" void kernel_launch(void* const* d_in, const int* in_sizes, int n_in,
                              void* d_out, int out_size) {
    const float* y   = (const float*)d_in[0];
    const float* F   = (const float*)d_in[1];
    const float* Hm  = (const float*)d_in[2];
    const float* W1  = (const float*)d_in[3];
    const float* b1  = (const float*)d_in[4];
    const float* Wg  = (const float*)d_in[5];   // [480,600]
    const float* Ug  = (const float*)d_in[6];   // [200,600]
    const float* bg  = (const float*)d_in[7];   // [2,600]
    const float* W2  = (const float*)d_in[8];   // [200,320]
    const float* b2  = (const float*)d_in[9];
    const float* W3  = (const float*)d_in[10];
    const float* b3  = (const float*)d_in[11];
    const float* hn0 = (const float*)d_in[12];
    float* out = (float*)d_out;

    float *gx, *gh, *a2, *hn, *prior, *post, *dm1y;
    __half *a1, *hnh, *WgTh, *WgTl, *UgTh, *UgTl, *W2Th, *W2Tl;
    cudaGetSymbolAddress((void**)&gx,   g_gx);
    cudaGetSymbolAddress((void**)&gh,   g_gh);
    cudaGetSymbolAddress((void**)&a2,   g_a2);
    cudaGetSymbolAddress((void**)&hn,   g_hn);
    cudaGetSymbolAddress((void**)&prior,g_prior);
    cudaGetSymbolAddress((void**)&post, g_post);
    cudaGetSymbolAddress((void**)&dm1y, g_dm1y);
    cudaGetSymbolAddress((void**)&a1,   g_a1);
    cudaGetSymbolAddress((void**)&hnh,  g_hnh);
    cudaGetSymbolAddress((void**)&WgTh, g_WgTh);
    cudaGetSymbolAddress((void**)&WgTl, g_WgTl);
    cudaGetSymbolAddress((void**)&UgTh, g_UgTh);
    cudaGetSymbolAddress((void**)&UgTl, g_UgTl);
    cudaGetSymbolAddress((void**)&W2Th, g_W2Th);
    cudaGetSymbolAddress((void**)&W2Tl, g_W2Tl);

    const int SMEM = 2 * STAGE;     // 73728
    cudaFuncSetAttribute(gemm_mma<false>,
                         cudaFuncAttributeMaxDynamicSharedMemorySize, SMEM);
    cudaFuncSetAttribute(gemm_mma<true>,
                         cudaFuncAttributeMaxDynamicSharedMemorySize, SMEM);

    wsplit_kernel<<<(H1*3*HID + 255)/256, 256>>>(Wg, WgTh, WgTl, H1, 3*HID);
    wsplit_kernel<<<(HID*3*HID + 255)/256, 256>>>(Ug, UgTh, UgTl, HID, 3*HID);
    wsplit_kernel<<<(HID*H2 + 255)/256, 256>>>(W2, W2Th, W2Tl, HID, H2);
    init_kernel<<<(BATCH*HID + 255)/256, 256>>>(hn0, hn, hnh, prior, post);

    feat_a1_kernel<<<BATCH/64, 256>>>(y, F, Hm, W1, b1, post, prior, dm1y, a1);

    for (int t = 0; t < T_STEPS; t++) {
        const float* hin = hn + (size_t)(t & 1) * BATCH * HID;
        float* hout      = hn + (size_t)((t + 1) & 1) * BATCH * HID;

        gemm_mma<false><<<dim3(10, BATCH/128), 256, SMEM>>>(
            a1, WgTh, WgTl, bg,          gx, 3*HID, H1);
        gemm_mma<false><<<dim3(10, BATCH/128), 256, SMEM>>>(
            hnh, UgTh, UgTl, bg + 3*HID, gh, 3*HID, HID);

        gru_gate_kernel<<<(BATCH*HID/2 + 255)/256, 256>>>(gx, gh, hin, hout, hnh);

        gemm_mma<true><<<dim3(5, BATCH/128), 256, SMEM>>>(
            hnh, W2Th, W2Tl, b2, a2, H2, HID);

        if (t + 1 < T_STEPS) {
            post_feat_kernel<<<BATCH/64, 256>>>(a2, W3, b3,
                y + (size_t)(t + 1) * BATCH * NDIM, F, Hm, W1, b1,
                prior, post, dm1y, out + (size_t)t * BATCH * MDIM, a1);
        } else {
            out_kernel<<<BATCH/32, 256>>>(a2, W3, b3, dm1y, prior, post,
                                          out + (size_t)t * BATCH * MDIM);
        }
    }
}

// round 9
// speedup vs baseline: 1.1760x; 1.0851x over previous
#include <cuda_runtime.h>
#include <cuda_fp16.h>
#include <cstdint>
#include <math.h>

#define T_STEPS 32
#define BATCH   8192
#define MDIM    4
#define NDIM    2
#define H1      480
#define HID     200
#define H2      320

// ---------------- scratch (device globals; no allocation allowed) -----------
__device__ float g_gx  [BATCH * 3 * HID];
__device__ float g_gh  [BATCH * 3 * HID];
__device__ float g_a2  [BATCH * H2];
__device__ float g_hn  [2 * BATCH * HID];
__device__ float g_prior[BATCH * MDIM];
__device__ float g_post [BATCH * MDIM];
__device__ float g_dm1y [BATCH * NDIM];
__device__ __half g_a1 [BATCH * H1];
__device__ __half g_hnh[BATCH * HID];
__device__ __half g_WgTh[3*HID*H1],  g_WgTl[3*HID*H1];
__device__ __half g_UgTh[3*HID*HID], g_UgTl[3*HID*HID];
__device__ __half g_W2Th[H2*HID],    g_W2Tl[H2*HID];

// ---------------- PTX helpers ------------------------------------------------
__device__ __forceinline__ uint32_t smem_u32(const void* p) {
    uint32_t a;
    asm("{ .reg .u64 t; cvta.to.shared.u64 t, %1; cvt.u32.u64 %0, t; }" : "=r"(a) : "l"(p));
    return a;
}
__device__ __forceinline__ void cp16(uint32_t dst, const void* src) {
    asm volatile("cp.async.cg.shared.global [%0], [%1], 16;" :: "r"(dst), "l"(src) : "memory");
}
__device__ __forceinline__ void sts_zero16(uint32_t addr) {
    asm volatile("st.shared.v4.b32 [%0], {%1,%1,%1,%1};" :: "r"(addr), "r"(0) : "memory");
}
__device__ __forceinline__ void ldsm4(uint32_t* r, uint32_t addr) {
    asm volatile("ldmatrix.sync.aligned.m8n8.x4.shared.b16 {%0,%1,%2,%3}, [%4];"
                 : "=r"(r[0]), "=r"(r[1]), "=r"(r[2]), "=r"(r[3]) : "r"(addr));
}
__device__ __forceinline__ void mma16816(float* c, const uint32_t* a, uint32_t b0, uint32_t b1) {
    asm volatile("mma.sync.aligned.m16n8k16.row.col.f32.f16.f16.f32 "
                 "{%0,%1,%2,%3}, {%4,%5,%6,%7}, {%8,%9}, {%0,%1,%2,%3};"
                 : "+f"(c[0]), "+f"(c[1]), "+f"(c[2]), "+f"(c[3])
                 : "r"(a[0]), "r"(a[1]), "r"(a[2]), "r"(a[3]), "r"(b0), "r"(b1));
}

// ---------------- split-fp16 HMMA GEMM (R5 proven config, occ=3) -------------
// C[128 x 64 tile] = A[M x K] @ (Bh+Bl)^T[N x K] + bias, fp32 out.
// A single fp16 plane; B hi+lo fp16 planes -> 2 MMA per K16.
// BK=64, 256 threads, 8 warps (4m x 2n), warp tile 32x32, 2-stage cp.async.
#define ROWB   144                    // 128B data + 16B pad (conflict-free ldmatrix)
#define A_PL   (128 * ROWB)           // 18432
#define B_PL   (64 * ROWB)            // 9216
#define STAGE  (A_PL + 2 * B_PL)      // 36864

template<bool RELU>
__global__ __launch_bounds__(256, 3)
void gemm_mma(const __half* __restrict__ A,
              const __half* __restrict__ Bh, const __half* __restrict__ Bl,
              const float* __restrict__ bias, float* __restrict__ C,
              int Ncols, int K) {
    extern __shared__ char smem[];
    const uint32_t s0 = smem_u32(smem);
    const int tid  = threadIdx.x;
    const int lane = tid & 31, wid = tid >> 5;
    const int wm = (wid & 3) * 32;
    const int wn = (wid >> 2) * 32;
    const int bm = blockIdx.y * 128;
    const int bn = blockIdx.x * 64;

    float acc[2][4][4];
    #pragma unroll
    for (int i = 0; i < 2; i++)
        #pragma unroll
        for (int j = 0; j < 4; j++)
            #pragma unroll
            for (int k = 0; k < 4; k++) acc[i][j][k] = 0.f;

    const int NC = (K + 63) / 64;

    auto load_stage = [&](int s) {
        uint32_t base = s0 + (uint32_t)(s & 1) * STAGE;
        int k0 = s * 64;
        int kc = K - k0; if (kc > 64) kc = 64;
        #pragma unroll
        for (int it = 0; it < 4; it++) {             // A: 128 rows x 8 chunks
            int idx = tid + it * 256;
            int r = idx >> 3, ch = idx & 7;
            uint32_t dst = base + (uint32_t)r * ROWB + (uint32_t)ch * 16;
            if (ch * 8 < kc)
                cp16(dst, A + (size_t)(bm + r) * K + k0 + ch * 8);
            else
                sts_zero16(dst);
        }
        #pragma unroll
        for (int it = 0; it < 4; it++) {             // B: 2 planes x 64 rows x 8 chunks
            int idx = tid + it * 256;
            int plane = idx >> 9, r = (idx >> 3) & 63, ch = idx & 7;
            uint32_t dst = base + A_PL + (uint32_t)plane * B_PL
                         + (uint32_t)r * ROWB + (uint32_t)ch * 16;
            if ((bn + r) < Ncols && ch * 8 < kc)
                cp16(dst, (plane ? Bl : Bh) + (size_t)(bn + r) * K + k0 + ch * 8);
            else
                sts_zero16(dst);
        }
        asm volatile("cp.async.commit_group;" ::: "memory");
    };

    load_stage(0);

    const uint32_t a_lrow = (uint32_t)(lane & 15) * ROWB + (uint32_t)(lane >> 4) * 16;
    const uint32_t b_lrow = (uint32_t)((lane & 7) + ((lane >> 3) & 1) * 8) * ROWB
                          + (uint32_t)(lane >> 4) * 16;

    for (int i = 0; i < NC; i++) {
        if (i + 1 < NC) {
            load_stage(i + 1);
            asm volatile("cp.async.wait_group 1;" ::: "memory");
        } else {
            asm volatile("cp.async.wait_group 0;" ::: "memory");
        }
        __syncthreads();

        uint32_t base = s0 + (uint32_t)(i & 1) * STAGE;
        uint32_t sA  = base;
        uint32_t sBh = base + A_PL, sBl = sBh + B_PL;

        #pragma unroll
        for (int ks = 0; ks < 4; ks++) {
            uint32_t koff = (uint32_t)ks * 32;       // 16 halves = 32B
            uint32_t a[2][4], bh[2][4], bl[2][4];
            #pragma unroll
            for (int fm = 0; fm < 2; fm++)
                ldsm4(a[fm], sA + (uint32_t)(wm + fm * 16) * ROWB + koff + a_lrow);
            #pragma unroll
            for (int np = 0; np < 2; np++) {
                uint32_t ro = (uint32_t)(wn + np * 16) * ROWB + koff + b_lrow;
                ldsm4(bh[np], sBh + ro);
                ldsm4(bl[np], sBl + ro);
            }
            #pragma unroll
            for (int fm = 0; fm < 2; fm++)
                #pragma unroll
                for (int j = 0; j < 4; j++) {
                    int np = j >> 1, sel = j & 1;
                    mma16816(acc[fm][j], a[fm], bh[np][sel], bh[np][sel + 2]);
                    mma16816(acc[fm][j], a[fm], bl[np][sel], bl[np][sel + 2]);
                }
        }
        __syncthreads();
    }

    const int qid = lane >> 2, qt = lane & 3;
    #pragma unroll
    for (int fm = 0; fm < 2; fm++) {
        int row = bm + wm + fm * 16 + qid;
        #pragma unroll
        for (int j = 0; j < 4; j++) {
            int col = bn + wn + j * 8 + qt * 2;
            if (col >= Ncols) continue;
            float b0 = __ldg(&bias[col]), b1 = __ldg(&bias[col + 1]);
            float2 v0 = make_float2(acc[fm][j][0] + b0, acc[fm][j][1] + b1);
            float2 v1 = make_float2(acc[fm][j][2] + b0, acc[fm][j][3] + b1);
            if (RELU) {
                v0.x = fmaxf(v0.x, 0.f); v0.y = fmaxf(v0.y, 0.f);
                v1.x = fmaxf(v1.x, 0.f); v1.y = fmaxf(v1.y, 0.f);
            }
            *(float2*)&C[(size_t)row * Ncols + col]       = v0;
            *(float2*)&C[(size_t)(row + 8) * Ncols + col] = v1;
        }
    }
}

// ---------------- small kernels ---------------------------------------------
__device__ __forceinline__ void wsplit_store(float v, __half* hi, __half* lo, size_t idx) {
    __half h = __float2half_rn(v);
    hi[idx] = h;
    lo[idx] = __float2half_rn(v - __half2float(h));
}

__global__ void init_kernel(const float* __restrict__ hn0, float* __restrict__ hn,
                            __half* __restrict__ hnh,
                            float* __restrict__ prior, float* __restrict__ post) {
    int i = blockIdx.x * blockDim.x + threadIdx.x;
    if (i < BATCH * HID) {
        float v = hn0[i];
        hn[i] = v;
        hnh[i] = __float2half_rn(v);
    }
    if (i < BATCH * MDIM) { prior[i] = 0.f; post[i] = 0.f; }
}

__global__ void wsplit_kernel(const float* __restrict__ in,
                              __half* __restrict__ oh, __half* __restrict__ ol,
                              int K, int N) {
    int i = blockIdx.x * blockDim.x + threadIdx.x;
    if (i < K * N) {
        int k = i / N, n = i % N;
        wsplit_store(in[i], oh, ol, (size_t)n * K + k);
    }
}

__global__ void feat_a1_kernel(const float* __restrict__ y_t,
                               const float* __restrict__ F, const float* __restrict__ Hm,
                               const float* __restrict__ W1, const float* __restrict__ b1,
                               const float* __restrict__ post, float* __restrict__ prior,
                               float* __restrict__ dm1y_out, __half* __restrict__ a1) {
    __shared__ float feat[64][9];
    int tid = threadIdx.x;
    int b0 = blockIdx.x * 64;
    if (tid < 64) {
        int b = b0 + tid;
        float p[4], pr_old[4];
        #pragma unroll
        for (int m = 0; m < 4; m++) { p[m] = post[b*4+m]; pr_old[m] = prior[b*4+m]; }
        float pn[4];
        #pragma unroll
        for (int i = 0; i < 4; i++) {
            float s = 0.f;
            #pragma unroll
            for (int j = 0; j < 4; j++) s += __ldg(&F[i*4+j]) * p[j];
            pn[i] = s;
        }
        float my[2];
        #pragma unroll
        for (int i = 0; i < 2; i++) {
            float s = 0.f;
            #pragma unroll
            for (int j = 0; j < 4; j++) s += __ldg(&Hm[i*4+j]) * pn[j];
            my[i] = s;
        }
        float dy0 = y_t[b*2+0] - my[0];
        float dy1 = y_t[b*2+1] - my[1];
        dm1y_out[b*2+0] = dy0;
        dm1y_out[b*2+1] = dy1;
        float inv_y = rsqrtf(fmaxf(dy0*dy0 + dy1*dy1, 1e-12f));
        feat[tid][0] = dy0*inv_y; feat[tid][1] = dy1*inv_y;
        feat[tid][2] = dy0*inv_y; feat[tid][3] = dy1*inv_y;
        float d[4], s2 = 0.f;
        #pragma unroll
        for (int m = 0; m < 4; m++) { d[m] = p[m] - pr_old[m]; s2 += d[m]*d[m]; }
        float inv_x = rsqrtf(fmaxf(s2, 1e-12f));
        #pragma unroll
        for (int m = 0; m < 4; m++) feat[tid][4+m] = d[m]*inv_x;
        #pragma unroll
        for (int m = 0; m < 4; m++) prior[b*4+m] = pn[m];
    }
    __syncthreads();
    for (int idx = tid; idx < 64 * H1; idx += 256) {
        int r = idx / H1, c = idx % H1;
        float s = __ldg(&b1[c]);
        #pragma unroll
        for (int k = 0; k < 8; k++) s += feat[r][k] * __ldg(&W1[k*H1 + c]);
        a1[(size_t)(b0 + r) * H1 + c] = __float2half_rn(fmaxf(s, 0.f));
    }
}

// GRU gate combine, float2-vectorized (HID=200 -> 100 pairs per row)
__global__ void gru_gate_kernel(const float* __restrict__ Gx, const float* __restrict__ Gh,
                                const float* __restrict__ h_in, float* __restrict__ h_out,
                                __half* __restrict__ hnh) {
    int idx = blockIdx.x * blockDim.x + threadIdx.x;     // pair index
    if (idx >= BATCH * HID / 2) return;
    int b = idx / (HID / 2), jp = idx % (HID / 2);
    const float* gx = Gx + (size_t)b * 3 * HID;
    const float* gh = Gh + (size_t)b * 3 * HID;
    int j = jp * 2;
    float2 xz = *(const float2*)&gx[j];
    float2 hz = *(const float2*)&gh[j];
    float2 xr = *(const float2*)&gx[j + HID];
    float2 hr = *(const float2*)&gh[j + HID];
    float2 xh = *(const float2*)&gx[j + 2*HID];
    float2 hh = *(const float2*)&gh[j + 2*HID];
    float2 h  = *(const float2*)&h_in[(size_t)b * HID + j];
    float z0 = 1.f / (1.f + __expf(-(xz.x + hz.x)));
    float z1 = 1.f / (1.f + __expf(-(xz.y + hz.y)));
    float r0 = 1.f / (1.f + __expf(-(xr.x + hr.x)));
    float r1 = 1.f / (1.f + __expf(-(xr.y + hr.y)));
    float c0 = tanhf(xh.x + r0 * hh.x);
    float c1 = tanhf(xh.y + r1 * hh.y);
    float v0 = z0 * h.x + (1.f - z0) * c0;
    float v1 = z1 * h.y + (1.f - z1) * c1;
    *(float2*)&h_out[(size_t)b * HID + j] = make_float2(v0, v1);
    __half2 hv; hv.x = __float2half_rn(v0); hv.y = __float2half_rn(v1);
    *(__half2*)&hnh[(size_t)b * HID + j] = hv;
}

__global__ void out_kernel(const float* __restrict__ a2, const float* __restrict__ W3,
                           const float* __restrict__ b3, const float* __restrict__ dm1y,
                           const float* __restrict__ prior, float* __restrict__ post,
                           float* __restrict__ out_t) {
    int tid = threadIdx.x;
    int lane = tid & 7;
    int b = blockIdx.x * 32 + (tid >> 3);
    float kg[8];
    #pragma unroll
    for (int o = 0; o < 8; o++) kg[o] = 0.f;
    const float* arow = a2 + (size_t)b * H2;
    for (int k = lane; k < H2; k += 8) {
        float a = arow[k];
        float4 w0 = *(const float4*)(W3 + k*8);
        float4 w1 = *(const float4*)(W3 + k*8 + 4);
        kg[0] = fmaf(a, w0.x, kg[0]); kg[1] = fmaf(a, w0.y, kg[1]);
        kg[2] = fmaf(a, w0.z, kg[2]); kg[3] = fmaf(a, w0.w, kg[3]);
        kg[4] = fmaf(a, w1.x, kg[4]); kg[5] = fmaf(a, w1.y, kg[5]);
        kg[6] = fmaf(a, w1.z, kg[6]); kg[7] = fmaf(a, w1.w, kg[7]);
    }
    #pragma unroll
    for (int off = 4; off > 0; off >>= 1)
        #pragma unroll
        for (int o = 0; o < 8; o++)
            kg[o] += __shfl_down_sync(0xFFFFFFFFu, kg[o], off, 8);
    if (lane == 0) {
        float dy0 = dm1y[b*2+0], dy1 = dm1y[b*2+1];
        #pragma unroll
        for (int m = 0; m < 4; m++) {
            float k0 = kg[2*m]   + __ldg(&b3[2*m]);
            float k1 = kg[2*m+1] + __ldg(&b3[2*m+1]);
            float pv = prior[b*4+m] + k0*dy0 + k1*dy1;
            post[b*4+m] = pv;
            out_t[b*4+m] = pv;
        }
    }
}

// ---------------- launch ----------------------------------------------------
extern "C" void kernel_launch(void* const* d_in, const int* in_sizes, int n_in,
                              void* d_out, int out_size) {
    const float* y   = (const float*)d_in[0];
    const float* F   = (const float*)d_in[1];
    const float* Hm  = (const float*)d_in[2];
    const float* W1  = (const float*)d_in[3];
    const float* b1  = (const float*)d_in[4];
    const float* Wg  = (const float*)d_in[5];   // [480,600]
    const float* Ug  = (const float*)d_in[6];   // [200,600]
    const float* bg  = (const float*)d_in[7];   // [2,600]
    const float* W2  = (const float*)d_in[8];   // [200,320]
    const float* b2  = (const float*)d_in[9];
    const float* W3  = (const float*)d_in[10];
    const float* b3  = (const float*)d_in[11];
    const float* hn0 = (const float*)d_in[12];
    float* out = (float*)d_out;

    float *gx, *gh, *a2, *hn, *prior, *post, *dm1y;
    __half *a1, *hnh, *WgTh, *WgTl, *UgTh, *UgTl, *W2Th, *W2Tl;
    cudaGetSymbolAddress((void**)&gx,   g_gx);
    cudaGetSymbolAddress((void**)&gh,   g_gh);
    cudaGetSymbolAddress((void**)&a2,   g_a2);
    cudaGetSymbolAddress((void**)&hn,   g_hn);
    cudaGetSymbolAddress((void**)&prior,g_prior);
    cudaGetSymbolAddress((void**)&post, g_post);
    cudaGetSymbolAddress((void**)&dm1y, g_dm1y);
    cudaGetSymbolAddress((void**)&a1,   g_a1);
    cudaGetSymbolAddress((void**)&hnh,  g_hnh);
    cudaGetSymbolAddress((void**)&WgTh, g_WgTh);
    cudaGetSymbolAddress((void**)&WgTl, g_WgTl);
    cudaGetSymbolAddress((void**)&UgTh, g_UgTh);
    cudaGetSymbolAddress((void**)&UgTl, g_UgTl);
    cudaGetSymbolAddress((void**)&W2Th, g_W2Th);
    cudaGetSymbolAddress((void**)&W2Tl, g_W2Tl);

    const int SMEM = 2 * STAGE;     // 73728
    cudaFuncSetAttribute(gemm_mma<false>,
                         cudaFuncAttributeMaxDynamicSharedMemorySize, SMEM);
    cudaFuncSetAttribute(gemm_mma<true>,
                         cudaFuncAttributeMaxDynamicSharedMemorySize, SMEM);

    wsplit_kernel<<<(H1*3*HID + 255)/256, 256>>>(Wg, WgTh, WgTl, H1, 3*HID);
    wsplit_kernel<<<(HID*3*HID + 255)/256, 256>>>(Ug, UgTh, UgTl, HID, 3*HID);
    wsplit_kernel<<<(HID*H2 + 255)/256, 256>>>(W2, W2Th, W2Tl, HID, H2);
    init_kernel<<<(BATCH*HID + 255)/256, 256>>>(hn0, hn, hnh, prior, post);

    for (int t = 0; t < T_STEPS; t++) {
        const float* hin = hn + (size_t)(t & 1) * BATCH * HID;
        float* hout      = hn + (size_t)((t + 1) & 1) * BATCH * HID;

        feat_a1_kernel<<<BATCH/64, 256>>>(y + (size_t)t*BATCH*NDIM, F, Hm, W1, b1,
                                          post, prior, dm1y, a1);

        gemm_mma<false><<<dim3(10, BATCH/128), 256, SMEM>>>(
            a1, WgTh, WgTl, bg,          gx, 3*HID, H1);
        gemm_mma<false><<<dim3(10, BATCH/128), 256, SMEM>>>(
            hnh, UgTh, UgTl, bg + 3*HID, gh, 3*HID, HID);

        gru_gate_kernel<<<(BATCH*HID/2 + 255)/256, 256>>>(gx, gh, hin, hout, hnh);

        gemm_mma<true><<<dim3(5, BATCH/128), 256, SMEM>>>(
            hnh, W2Th, W2Tl, b2, a2, H2, HID);

        out_kernel<<<BATCH/32, 256>>>(a2, W3, b3, dm1y, prior, post,
                                      out + (size_t)t*BATCH*MDIM);
    }
}

// round 11
// speedup vs baseline: 1.2679x; 1.0781x over previous
#include <cuda_runtime.h>
#include <cuda_fp16.h>
#include <cstdint>
#include <math.h>

#define T_STEPS 32
#define BATCH   8192
#define MDIM    4
#define NDIM    2
#define H1      480
#define HID     200
#define H2      320

// ---------------- scratch (device globals; no allocation allowed) -----------
__device__ float g_gx  [BATCH * 3 * HID];
__device__ float g_gh  [BATCH * 3 * HID];
__device__ float g_a2  [BATCH * H2];
__device__ float g_hn  [2 * BATCH * HID];
__device__ float g_prior[BATCH * MDIM];
__device__ float g_post [BATCH * MDIM];
__device__ float g_dm1y [BATCH * NDIM];
__device__ __half g_a1 [BATCH * H1];
__device__ __half g_hnh[BATCH * HID];
__device__ __half g_WgTh[3*HID*H1],  g_WgTl[3*HID*H1];
__device__ __half g_UgTh[3*HID*HID], g_UgTl[3*HID*HID];
__device__ __half g_W2Th[H2*HID],    g_W2Tl[H2*HID];

// ---------------- PTX helpers ------------------------------------------------
__device__ __forceinline__ uint32_t smem_u32(const void* p) {
    uint32_t a;
    asm("{ .reg .u64 t; cvta.to.shared.u64 t, %1; cvt.u32.u64 %0, t; }" : "=r"(a) : "l"(p));
    return a;
}
__device__ __forceinline__ void cp16(uint32_t dst, const void* src) {
    asm volatile("cp.async.cg.shared.global [%0], [%1], 16;" :: "r"(dst), "l"(src) : "memory");
}
__device__ __forceinline__ void sts_zero16(uint32_t addr) {
    asm volatile("st.shared.v4.b32 [%0], {%1,%1,%1,%1};" :: "r"(addr), "r"(0) : "memory");
}
__device__ __forceinline__ void ldsm4(uint32_t* r, uint32_t addr) {
    asm volatile("ldmatrix.sync.aligned.m8n8.x4.shared.b16 {%0,%1,%2,%3}, [%4];"
                 : "=r"(r[0]), "=r"(r[1]), "=r"(r[2]), "=r"(r[3]) : "r"(addr));
}
__device__ __forceinline__ void mma16816(float* c, const uint32_t* a, uint32_t b0, uint32_t b1) {
    asm volatile("mma.sync.aligned.m16n8k16.row.col.f32.f16.f16.f32 "
                 "{%0,%1,%2,%3}, {%4,%5,%6,%7}, {%8,%9}, {%0,%1,%2,%3};"
                 : "+f"(c[0]), "+f"(c[1]), "+f"(c[2]), "+f"(c[3])
                 : "r"(a[0]), "r"(a[1]), "r"(a[2]), "r"(a[3]), "r"(b0), "r"(b1));
}

// ---------------- split-fp16 HMMA GEMM core ----------------------------------
// C[128 x 64 tile] = A[M x K] @ (Bh+Bl)^T[N x K] + bias, fp32 out.
// BK=64, 256 threads, 8 warps (4m x 2n), warp tile 32x32, 2-stage cp.async.
#define ROWB   144                    // 128B data + 16B pad (conflict-free ldmatrix)
#define A_PL   (128 * ROWB)           // 18432
#define B_PL   (64 * ROWB)            // 9216
#define STAGE  (A_PL + 2 * B_PL)      // 36864

template<bool RELU>
__device__ __forceinline__ void gemm_body(
        const __half* __restrict__ A,
        const __half* __restrict__ Bh, const __half* __restrict__ Bl,
        const float* __restrict__ bias, float* __restrict__ C,
        int Ncols, int K, int bm, int bn, uint32_t s0) {
    const int tid  = threadIdx.x;
    const int lane = tid & 31, wid = tid >> 5;
    const int wm = (wid & 3) * 32;
    const int wn = (wid >> 2) * 32;

    float acc[2][4][4];
    #pragma unroll
    for (int i = 0; i < 2; i++)
        #pragma unroll
        for (int j = 0; j < 4; j++)
            #pragma unroll
            for (int k = 0; k < 4; k++) acc[i][j][k] = 0.f;

    const int NC = (K + 63) / 64;

    auto load_stage = [&](int s) {
        uint32_t base = s0 + (uint32_t)(s & 1) * STAGE;
        int k0 = s * 64;
        int kc = K - k0; if (kc > 64) kc = 64;
        #pragma unroll
        for (int it = 0; it < 4; it++) {             // A: 128 rows x 8 chunks
            int idx = tid + it * 256;
            int r = idx >> 3, ch = idx & 7;
            uint32_t dst = base + (uint32_t)r * ROWB + (uint32_t)ch * 16;
            if (ch * 8 < kc)
                cp16(dst, A + (size_t)(bm + r) * K + k0 + ch * 8);
            else
                sts_zero16(dst);
        }
        #pragma unroll
        for (int it = 0; it < 4; it++) {             // B: 2 planes x 64 rows x 8 chunks
            int idx = tid + it * 256;
            int plane = idx >> 9, r = (idx >> 3) & 63, ch = idx & 7;
            uint32_t dst = base + A_PL + (uint32_t)plane * B_PL
                         + (uint32_t)r * ROWB + (uint32_t)ch * 16;
            if ((bn + r) < Ncols && ch * 8 < kc)
                cp16(dst, (plane ? Bl : Bh) + (size_t)(bn + r) * K + k0 + ch * 8);
            else
                sts_zero16(dst);
        }
        asm volatile("cp.async.commit_group;" ::: "memory");
    };

    load_stage(0);

    const uint32_t a_lrow = (uint32_t)(lane & 15) * ROWB + (uint32_t)(lane >> 4) * 16;
    const uint32_t b_lrow = (uint32_t)((lane & 7) + ((lane >> 3) & 1) * 8) * ROWB
                          + (uint32_t)(lane >> 4) * 16;

    for (int i = 0; i < NC; i++) {
        if (i + 1 < NC) {
            load_stage(i + 1);
            asm volatile("cp.async.wait_group 1;" ::: "memory");
        } else {
            asm volatile("cp.async.wait_group 0;" ::: "memory");
        }
        __syncthreads();

        uint32_t base = s0 + (uint32_t)(i & 1) * STAGE;
        uint32_t sA  = base;
        uint32_t sBh = base + A_PL, sBl = sBh + B_PL;

        #pragma unroll
        for (int ks = 0; ks < 4; ks++) {
            uint32_t koff = (uint32_t)ks * 32;       // 16 halves = 32B
            uint32_t a[2][4], bh[2][4], bl[2][4];
            #pragma unroll
            for (int fm = 0; fm < 2; fm++)
                ldsm4(a[fm], sA + (uint32_t)(wm + fm * 16) * ROWB + koff + a_lrow);
            #pragma unroll
            for (int np = 0; np < 2; np++) {
                uint32_t ro = (uint32_t)(wn + np * 16) * ROWB + koff + b_lrow;
                ldsm4(bh[np], sBh + ro);
                ldsm4(bl[np], sBl + ro);
            }
            #pragma unroll
            for (int fm = 0; fm < 2; fm++)
                #pragma unroll
                for (int j = 0; j < 4; j++) {
                    int np = j >> 1, sel = j & 1;
                    mma16816(acc[fm][j], a[fm], bh[np][sel], bh[np][sel + 2]);
                    mma16816(acc[fm][j], a[fm], bl[np][sel], bl[np][sel + 2]);
                }
        }
        __syncthreads();
    }

    const int qid = lane >> 2, qt = lane & 3;
    #pragma unroll
    for (int fm = 0; fm < 2; fm++) {
        int row = bm + wm + fm * 16 + qid;
        #pragma unroll
        for (int j = 0; j < 4; j++) {
            int col = bn + wn + j * 8 + qt * 2;
            if (col >= Ncols) continue;
            float b0 = __ldg(&bias[col]), b1 = __ldg(&bias[col + 1]);
            float2 v0 = make_float2(acc[fm][j][0] + b0, acc[fm][j][1] + b1);
            float2 v1 = make_float2(acc[fm][j][2] + b0, acc[fm][j][3] + b1);
            if (RELU) {
                v0.x = fmaxf(v0.x, 0.f); v0.y = fmaxf(v0.y, 0.f);
                v1.x = fmaxf(v1.x, 0.f); v1.y = fmaxf(v1.y, 0.f);
            }
            *(float2*)&C[(size_t)row * Ncols + col]       = v0;
            *(float2*)&C[(size_t)(row + 8) * Ncols + col] = v1;
        }
    }
}

// merged GEMM1 (a1@Wg -> gx) + GEMM2 (hnh@Ug -> gh): one grid, dispatch on y.
__global__ __launch_bounds__(256, 3)
void gemm_dual(const __half* __restrict__ A1, const __half* __restrict__ Bh1,
               const __half* __restrict__ Bl1, const float* __restrict__ bias1,
               float* __restrict__ C1,
               const __half* __restrict__ A2, const __half* __restrict__ Bh2,
               const __half* __restrict__ Bl2, const float* __restrict__ bias2,
               float* __restrict__ C2) {
    extern __shared__ char smem[];
    const uint32_t s0 = smem_u32(smem);
    const bool second = blockIdx.y >= (BATCH / 128);
    const int bm = (blockIdx.y & (BATCH / 128 - 1)) * 128;
    const int bn = blockIdx.x * 64;
    if (!second)
        gemm_body<false>(A1, Bh1, Bl1, bias1, C1, 3 * HID, H1,  bm, bn, s0);
    else
        gemm_body<false>(A2, Bh2, Bl2, bias2, C2, 3 * HID, HID, bm, bn, s0);
}

__global__ __launch_bounds__(256, 3)
void gemm_single_relu(const __half* __restrict__ A, const __half* __restrict__ Bh,
                      const __half* __restrict__ Bl, const float* __restrict__ bias,
                      float* __restrict__ C, int Ncols, int K) {
    extern __shared__ char smem[];
    gemm_body<true>(A, Bh, Bl, bias, C, Ncols, K,
                    blockIdx.y * 128, blockIdx.x * 64, smem_u32(smem));
}

// ---------------- small kernels ---------------------------------------------
__device__ __forceinline__ void wsplit_store(float v, __half* hi, __half* lo, size_t idx) {
    __half h = __float2half_rn(v);
    hi[idx] = h;
    lo[idx] = __float2half_rn(v - __half2float(h));
}

__global__ void init_kernel(const float* __restrict__ hn0, float* __restrict__ hn,
                            __half* __restrict__ hnh,
                            float* __restrict__ prior, float* __restrict__ post) {
    int i = blockIdx.x * blockDim.x + threadIdx.x;
    if (i < BATCH * HID) {
        float v = hn0[i];
        hn[i] = v;
        hnh[i] = __float2half_rn(v);
    }
    if (i < BATCH * MDIM) { prior[i] = 0.f; post[i] = 0.f; }
}

__global__ void wsplit_kernel(const float* __restrict__ in,
                              __half* __restrict__ oh, __half* __restrict__ ol,
                              int K, int N) {
    int i = blockIdx.x * blockDim.x + threadIdx.x;
    if (i < K * N) {
        int k = i / N, n = i % N;
        wsplit_store(in[i], oh, ol, (size_t)n * K + k);
    }
}

__global__ void feat_a1_kernel(const float* __restrict__ y_t,
                               const float* __restrict__ F, const float* __restrict__ Hm,
                               const float* __restrict__ W1, const float* __restrict__ b1,
                               const float* __restrict__ post, float* __restrict__ prior,
                               float* __restrict__ dm1y_out, __half* __restrict__ a1) {
    __shared__ float feat[64][9];
    int tid = threadIdx.x;
    int b0 = blockIdx.x * 64;
    if (tid < 64) {
        int b = b0 + tid;
        float p[4], pr_old[4];
        #pragma unroll
        for (int m = 0; m < 4; m++) { p[m] = post[b*4+m]; pr_old[m] = prior[b*4+m]; }
        float pn[4];
        #pragma unroll
        for (int i = 0; i < 4; i++) {
            float s = 0.f;
            #pragma unroll
            for (int j = 0; j < 4; j++) s += __ldg(&F[i*4+j]) * p[j];
            pn[i] = s;
        }
        float my[2];
        #pragma unroll
        for (int i = 0; i < 2; i++) {
            float s = 0.f;
            #pragma unroll
            for (int j = 0; j < 4; j++) s += __ldg(&Hm[i*4+j]) * pn[j];
            my[i] = s;
        }
        float dy0 = y_t[b*2+0] - my[0];
        float dy1 = y_t[b*2+1] - my[1];
        dm1y_out[b*2+0] = dy0;
        dm1y_out[b*2+1] = dy1;
        float inv_y = rsqrtf(fmaxf(dy0*dy0 + dy1*dy1, 1e-12f));
        feat[tid][0] = dy0*inv_y; feat[tid][1] = dy1*inv_y;
        feat[tid][2] = dy0*inv_y; feat[tid][3] = dy1*inv_y;
        float d[4], s2 = 0.f;
        #pragma unroll
        for (int m = 0; m < 4; m++) { d[m] = p[m] - pr_old[m]; s2 += d[m]*d[m]; }
        float inv_x = rsqrtf(fmaxf(s2, 1e-12f));
        #pragma unroll
        for (int m = 0; m < 4; m++) feat[tid][4+m] = d[m]*inv_x;
        #pragma unroll
        for (int m = 0; m < 4; m++) prior[b*4+m] = pn[m];
    }
    __syncthreads();
    for (int idx = tid; idx < 64 * H1; idx += 256) {
        int r = idx / H1, c = idx % H1;
        float s = __ldg(&b1[c]);
        #pragma unroll
        for (int k = 0; k < 8; k++) s += feat[r][k] * __ldg(&W1[k*H1 + c]);
        a1[(size_t)(b0 + r) * H1 + c] = __float2half_rn(fmaxf(s, 0.f));
    }
}

// GRU gate combine, float2-vectorized (HID=200 -> 100 pairs per row)
__global__ void gru_gate_kernel(const float* __restrict__ Gx, const float* __restrict__ Gh,
                                const float* __restrict__ h_in, float* __restrict__ h_out,
                                __half* __restrict__ hnh) {
    int idx = blockIdx.x * blockDim.x + threadIdx.x;     // pair index
    if (idx >= BATCH * HID / 2) return;
    int b = idx / (HID / 2), jp = idx % (HID / 2);
    const float* gx = Gx + (size_t)b * 3 * HID;
    const float* gh = Gh + (size_t)b * 3 * HID;
    int j = jp * 2;
    float2 xz = *(const float2*)&gx[j];
    float2 hz = *(const float2*)&gh[j];
    float2 xr = *(const float2*)&gx[j + HID];
    float2 hr = *(const float2*)&gh[j + HID];
    float2 xh = *(const float2*)&gx[j + 2*HID];
    float2 hh = *(const float2*)&gh[j + 2*HID];
    float2 h  = *(const float2*)&h_in[(size_t)b * HID + j];
    float z0 = 1.f / (1.f + __expf(-(xz.x + hz.x)));
    float z1 = 1.f / (1.f + __expf(-(xz.y + hz.y)));
    float r0 = 1.f / (1.f + __expf(-(xr.x + hr.x)));
    float r1 = 1.f / (1.f + __expf(-(xr.y + hr.y)));
    float c0 = tanhf(xh.x + r0 * hh.x);
    float c1 = tanhf(xh.y + r1 * hh.y);
    float v0 = z0 * h.x + (1.f - z0) * c0;
    float v1 = z1 * h.y + (1.f - z1) * c1;
    *(float2*)&h_out[(size_t)b * HID + j] = make_float2(v0, v1);
    __half2 hv; hv.x = __float2half_rn(v0); hv.y = __float2half_rn(v1);
    *(__half2*)&hnh[(size_t)b * HID + j] = hv;
}

__global__ void out_kernel(const float* __restrict__ a2, const float* __restrict__ W3,
                           const float* __restrict__ b3, const float* __restrict__ dm1y,
                           const float* __restrict__ prior, float* __restrict__ post,
                           float* __restrict__ out_t) {
    int tid = threadIdx.x;
    int lane = tid & 7;
    int b = blockIdx.x * 32 + (tid >> 3);
    float kg[8];
    #pragma unroll
    for (int o = 0; o < 8; o++) kg[o] = 0.f;
    const float* arow = a2 + (size_t)b * H2;
    for (int k = lane; k < H2; k += 8) {
        float a = arow[k];
        float4 w0 = *(const float4*)(W3 + k*8);
        float4 w1 = *(const float4*)(W3 + k*8 + 4);
        kg[0] = fmaf(a, w0.x, kg[0]); kg[1] = fmaf(a, w0.y, kg[1]);
        kg[2] = fmaf(a, w0.z, kg[2]); kg[3] = fmaf(a, w0.w, kg[3]);
        kg[4] = fmaf(a, w1.x, kg[4]); kg[5] = fmaf(a, w1.y, kg[5]);
        kg[6] = fmaf(a, w1.z, kg[6]); kg[7] = fmaf(a, w1.w, kg[7]);
    }
    #pragma unroll
    for (int off = 4; off > 0; off >>= 1)
        #pragma unroll
        for (int o = 0; o < 8; o++)
            kg[o] += __shfl_down_sync(0xFFFFFFFFu, kg[o], off, 8);
    if (lane == 0) {
        float dy0 = dm1y[b*2+0], dy1 = dm1y[b*2+1];
        #pragma unroll
        for (int m = 0; m < 4; m++) {
            float k0 = kg[2*m]   + __ldg(&b3[2*m]);
            float k1 = kg[2*m+1] + __ldg(&b3[2*m+1]);
            float pv = prior[b*4+m] + k0*dy0 + k1*dy1;
            post[b*4+m] = pv;
            out_t[b*4+m] = pv;
        }
    }
}

// ---------------- launch ----------------------------------------------------
extern "C" void kernel_launch(void* const* d_in, const int* in_sizes, int n_in,
                              void* d_out, int out_size) {
    const float* y   = (const float*)d_in[0];
    const float* F   = (const float*)d_in[1];
    const float* Hm  = (const float*)d_in[2];
    const float* W1  = (const float*)d_in[3];
    const float* b1  = (const float*)d_in[4];
    const float* Wg  = (const float*)d_in[5];   // [480,600]
    const float* Ug  = (const float*)d_in[6];   // [200,600]
    const float* bg  = (const float*)d_in[7];   // [2,600]
    const float* W2  = (const float*)d_in[8];   // [200,320]
    const float* b2  = (const float*)d_in[9];
    const float* W3  = (const float*)d_in[10];
    const float* b3  = (const float*)d_in[11];
    const float* hn0 = (const float*)d_in[12];
    float* out = (float*)d_out;

    float *gx, *gh, *a2, *hn, *prior, *post, *dm1y;
    __half *a1, *hnh, *WgTh, *WgTl, *UgTh, *UgTl, *W2Th, *W2Tl;
    cudaGetSymbolAddress((void**)&gx,   g_gx);
    cudaGetSymbolAddress((void**)&gh,   g_gh);
    cudaGetSymbolAddress((void**)&a2,   g_a2);
    cudaGetSymbolAddress((void**)&hn,   g_hn);
    cudaGetSymbolAddress((void**)&prior,g_prior);
    cudaGetSymbolAddress((void**)&post, g_post);
    cudaGetSymbolAddress((void**)&dm1y, g_dm1y);
    cudaGetSymbolAddress((void**)&a1,   g_a1);
    cudaGetSymbolAddress((void**)&hnh,  g_hnh);
    cudaGetSymbolAddress((void**)&WgTh, g_WgTh);
    cudaGetSymbolAddress((void**)&WgTl, g_WgTl);
    cudaGetSymbolAddress((void**)&UgTh, g_UgTh);
    cudaGetSymbolAddress((void**)&UgTl, g_UgTl);
    cudaGetSymbolAddress((void**)&W2Th, g_W2Th);
    cudaGetSymbolAddress((void**)&W2Tl, g_W2Tl);

    const int SMEM = 2 * STAGE;     // 73728
    cudaFuncSetAttribute(gemm_dual,
                         cudaFuncAttributeMaxDynamicSharedMemorySize, SMEM);
    cudaFuncSetAttribute(gemm_single_relu,
                         cudaFuncAttributeMaxDynamicSharedMemorySize, SMEM);

    wsplit_kernel<<<(H1*3*HID + 255)/256, 256>>>(Wg, WgTh, WgTl, H1, 3*HID);
    wsplit_kernel<<<(HID*3*HID + 255)/256, 256>>>(Ug, UgTh, UgTl, HID, 3*HID);
    wsplit_kernel<<<(HID*H2 + 255)/256, 256>>>(W2, W2Th, W2Tl, HID, H2);
    init_kernel<<<(BATCH*HID + 255)/256, 256>>>(hn0, hn, hnh, prior, post);

    for (int t = 0; t < T_STEPS; t++) {
        const float* hin = hn + (size_t)(t & 1) * BATCH * HID;
        float* hout      = hn + (size_t)((t + 1) & 1) * BATCH * HID;

        feat_a1_kernel<<<BATCH/64, 256>>>(y + (size_t)t*BATCH*NDIM, F, Hm, W1, b1,
                                          post, prior, dm1y, a1);

        gemm_dual<<<dim3(10, 2 * (BATCH/128)), 256, SMEM>>>(
            a1,  WgTh, WgTl, bg,         gx,
            hnh, UgTh, UgTl, bg + 3*HID, gh);

        gru_gate_kernel<<<(BATCH*HID/2 + 255)/256, 256>>>(gx, gh, hin, hout, hnh);

        gemm_single_relu<<<dim3(5, BATCH/128), 256, SMEM>>>(
            hnh, W2Th, W2Tl, b2, a2, H2, HID);

        out_kernel<<<BATCH/32, 256>>>(a2, W3, b3, dm1y, prior, post,
                                      out + (size_t)t*BATCH*MDIM);
    }
}

// round 12
// speedup vs baseline: 1.3505x; 1.0652x over previous
#include <cuda_runtime.h>
#include <cuda_fp16.h>
#include <cstdint>
#include <math.h>

#define T_STEPS 32
#define BATCH   8192
#define MDIM    4
#define NDIM    2
#define H1      480
#define HID     200
#define H2      320

// ---------------- scratch (device globals; no allocation allowed) -----------
__device__ float g_gx  [BATCH * 3 * HID];
__device__ float g_gh  [BATCH * 3 * HID];
__device__ float g_a2  [BATCH * H2];
__device__ float g_hn  [2 * BATCH * HID];
__device__ float g_prior[BATCH * MDIM];
__device__ float g_post [BATCH * MDIM];
__device__ float g_dm1y [BATCH * NDIM];
__device__ __half g_a1 [BATCH * H1];
__device__ __half g_hnh[BATCH * HID];
__device__ __half g_WgTh[3*HID*H1],  g_WgTl[3*HID*H1];
__device__ __half g_UgTh[3*HID*HID], g_UgTl[3*HID*HID];
__device__ __half g_W2Th[H2*HID],    g_W2Tl[H2*HID];

// ---------------- PTX helpers ------------------------------------------------
__device__ __forceinline__ uint32_t smem_u32(const void* p) {
    uint32_t a;
    asm("{ .reg .u64 t; cvta.to.shared.u64 t, %1; cvt.u32.u64 %0, t; }" : "=r"(a) : "l"(p));
    return a;
}
__device__ __forceinline__ void cp16(uint32_t dst, const void* src) {
    asm volatile("cp.async.cg.shared.global [%0], [%1], 16;" :: "r"(dst), "l"(src) : "memory");
}
__device__ __forceinline__ void sts_zero16(uint32_t addr) {
    asm volatile("st.shared.v4.b32 [%0], {%1,%1,%1,%1};" :: "r"(addr), "r"(0) : "memory");
}
__device__ __forceinline__ void ldsm4(uint32_t* r, uint32_t addr) {
    asm volatile("ldmatrix.sync.aligned.m8n8.x4.shared.b16 {%0,%1,%2,%3}, [%4];"
                 : "=r"(r[0]), "=r"(r[1]), "=r"(r[2]), "=r"(r[3]) : "r"(addr));
}
__device__ __forceinline__ void mma16816(float* c, const uint32_t* a, uint32_t b0, uint32_t b1) {
    asm volatile("mma.sync.aligned.m16n8k16.row.col.f32.f16.f16.f32 "
                 "{%0,%1,%2,%3}, {%4,%5,%6,%7}, {%8,%9}, {%0,%1,%2,%3};"
                 : "+f"(c[0]), "+f"(c[1]), "+f"(c[2]), "+f"(c[3])
                 : "r"(a[0]), "r"(a[1]), "r"(a[2]), "r"(a[3]), "r"(b0), "r"(b1));
}

// ---------------- split-fp16 HMMA GEMM core ----------------------------------
// C[128 x 64 tile] = A[M x K] @ (Bh+Bl)^T[N x K] + bias, fp32 out.
// BK=64, 256 threads, 8 warps (4m x 2n), warp tile 32x32, 2-stage cp.async.
// K compile-time: tail chunk trims both stage-fill and MMA steps.
#define ROWB   144                    // 128B data + 16B pad (conflict-free ldmatrix)
#define A_PL   (128 * ROWB)           // 18432
#define B_PL   (64 * ROWB)            // 9216
#define STAGE  (A_PL + 2 * B_PL)      // 36864

template<int K, bool RELU>
__device__ __forceinline__ void gemm_body(
        const __half* __restrict__ A,
        const __half* __restrict__ Bh, const __half* __restrict__ Bl,
        const float* __restrict__ bias, float* __restrict__ C,
        int Ncols, int bm, int bn, uint32_t s0) {
    constexpr int NC       = (K + 63) / 64;
    constexpr int TAIL     = K % 64;                      // 32 for 480, 8 for 200
    constexpr int TAIL_NKS = TAIL ? (TAIL + 15) / 16 : 4; // K16 steps on tail chunk
    constexpr int TAIL_CH  = TAIL ? TAIL_NKS * 2 : 8;     // 16B chunks actually read

    const int tid  = threadIdx.x;
    const int lane = tid & 31, wid = tid >> 5;
    const int wm = (wid & 3) * 32;
    const int wn = (wid >> 2) * 32;

    float acc[2][4][4];
    #pragma unroll
    for (int i = 0; i < 2; i++)
        #pragma unroll
        for (int j = 0; j < 4; j++)
            #pragma unroll
            for (int k = 0; k < 4; k++) acc[i][j][k] = 0.f;

    auto load_stage = [&](int s) {
        uint32_t base = s0 + (uint32_t)(s & 1) * STAGE;
        int k0 = s * 64;
        const bool last = TAIL && (s == NC - 1);
        const int kcc   = last ? TAIL : 64;
        const int chlim = last ? TAIL_CH : 8;
        #pragma unroll
        for (int it = 0; it < 4; it++) {             // A: 128 rows x 8 chunks
            int idx = tid + it * 256;
            int r = idx >> 3, ch = idx & 7;
            if (ch < chlim) {
                uint32_t dst = base + (uint32_t)r * ROWB + (uint32_t)ch * 16;
                if (ch * 8 < kcc)
                    cp16(dst, A + (size_t)(bm + r) * K + k0 + ch * 8);
                else
                    sts_zero16(dst);
            }
        }
        #pragma unroll
        for (int it = 0; it < 4; it++) {             // B: 2 planes x 64 rows x 8 chunks
            int idx = tid + it * 256;
            int plane = idx >> 9, r = (idx >> 3) & 63, ch = idx & 7;
            if (ch < chlim) {
                uint32_t dst = base + A_PL + (uint32_t)plane * B_PL
                             + (uint32_t)r * ROWB + (uint32_t)ch * 16;
                if ((bn + r) < Ncols && ch * 8 < kcc)
                    cp16(dst, (plane ? Bl : Bh) + (size_t)(bn + r) * K + k0 + ch * 8);
                else
                    sts_zero16(dst);
            }
        }
        asm volatile("cp.async.commit_group;" ::: "memory");
    };

    load_stage(0);

    const uint32_t a_lrow = (uint32_t)(lane & 15) * ROWB + (uint32_t)(lane >> 4) * 16;
    const uint32_t b_lrow = (uint32_t)((lane & 7) + ((lane >> 3) & 1) * 8) * ROWB
                          + (uint32_t)(lane >> 4) * 16;

    #pragma unroll
    for (int i = 0; i < NC; i++) {
        if (i + 1 < NC) {
            load_stage(i + 1);
            asm volatile("cp.async.wait_group 1;" ::: "memory");
        } else {
            asm volatile("cp.async.wait_group 0;" ::: "memory");
        }
        __syncthreads();

        uint32_t base = s0 + (uint32_t)(i & 1) * STAGE;
        uint32_t sA  = base;
        uint32_t sBh = base + A_PL, sBl = sBh + B_PL;

        const int nks = (TAIL && i == NC - 1) ? TAIL_NKS : 4;
        #pragma unroll
        for (int ks = 0; ks < 4; ks++) {
            if (ks >= nks) break;
            uint32_t koff = (uint32_t)ks * 32;       // 16 halves = 32B
            uint32_t a[2][4], bh[2][4], bl[2][4];
            #pragma unroll
            for (int fm = 0; fm < 2; fm++)
                ldsm4(a[fm], sA + (uint32_t)(wm + fm * 16) * ROWB + koff + a_lrow);
            #pragma unroll
            for (int np = 0; np < 2; np++) {
                uint32_t ro = (uint32_t)(wn + np * 16) * ROWB + koff + b_lrow;
                ldsm4(bh[np], sBh + ro);
                ldsm4(bl[np], sBl + ro);
            }
            #pragma unroll
            for (int fm = 0; fm < 2; fm++)
                #pragma unroll
                for (int j = 0; j < 4; j++) {
                    int np = j >> 1, sel = j & 1;
                    mma16816(acc[fm][j], a[fm], bh[np][sel], bh[np][sel + 2]);
                    mma16816(acc[fm][j], a[fm], bl[np][sel], bl[np][sel + 2]);
                }
        }
        __syncthreads();
    }

    const int qid = lane >> 2, qt = lane & 3;
    #pragma unroll
    for (int fm = 0; fm < 2; fm++) {
        int row = bm + wm + fm * 16 + qid;
        #pragma unroll
        for (int j = 0; j < 4; j++) {
            int col = bn + wn + j * 8 + qt * 2;
            if (col >= Ncols) continue;
            float b0 = __ldg(&bias[col]), b1 = __ldg(&bias[col + 1]);
            float2 v0 = make_float2(acc[fm][j][0] + b0, acc[fm][j][1] + b1);
            float2 v1 = make_float2(acc[fm][j][2] + b0, acc[fm][j][3] + b1);
            if (RELU) {
                v0.x = fmaxf(v0.x, 0.f); v0.y = fmaxf(v0.y, 0.f);
                v1.x = fmaxf(v1.x, 0.f); v1.y = fmaxf(v1.y, 0.f);
            }
            *(float2*)&C[(size_t)row * Ncols + col]       = v0;
            *(float2*)&C[(size_t)(row + 8) * Ncols + col] = v1;
        }
    }
}

// merged GEMM1 (a1@Wg -> gx, K=480) + GEMM2 (hnh@Ug -> gh, K=200)
__global__ __launch_bounds__(256, 3)
void gemm_dual(const __half* __restrict__ A1, const __half* __restrict__ Bh1,
               const __half* __restrict__ Bl1, const float* __restrict__ bias1,
               float* __restrict__ C1,
               const __half* __restrict__ A2, const __half* __restrict__ Bh2,
               const __half* __restrict__ Bl2, const float* __restrict__ bias2,
               float* __restrict__ C2) {
    extern __shared__ char smem[];
    const uint32_t s0 = smem_u32(smem);
    const bool second = blockIdx.y >= (BATCH / 128);
    const int bm = (blockIdx.y & (BATCH / 128 - 1)) * 128;
    const int bn = blockIdx.x * 64;
    if (!second)
        gemm_body<H1,  false>(A1, Bh1, Bl1, bias1, C1, 3 * HID, bm, bn, s0);
    else
        gemm_body<HID, false>(A2, Bh2, Bl2, bias2, C2, 3 * HID, bm, bn, s0);
}

// GEMM3: hnh@W2 -> a2, K=200, relu
__global__ __launch_bounds__(256, 3)
void gemm_single_relu(const __half* __restrict__ A, const __half* __restrict__ Bh,
                      const __half* __restrict__ Bl, const float* __restrict__ bias,
                      float* __restrict__ C, int Ncols) {
    extern __shared__ char smem[];
    gemm_body<HID, true>(A, Bh, Bl, bias, C, Ncols,
                         blockIdx.y * 128, blockIdx.x * 64, smem_u32(smem));
}

// ---------------- small kernels ---------------------------------------------
__device__ __forceinline__ void wsplit_store(float v, __half* hi, __half* lo, size_t idx) {
    __half h = __float2half_rn(v);
    hi[idx] = h;
    lo[idx] = __float2half_rn(v - __half2float(h));
}

__global__ void init_kernel(const float* __restrict__ hn0, float* __restrict__ hn,
                            __half* __restrict__ hnh,
                            float* __restrict__ prior, float* __restrict__ post) {
    int i = blockIdx.x * blockDim.x + threadIdx.x;
    if (i < BATCH * HID) {
        float v = hn0[i];
        hn[i] = v;
        hnh[i] = __float2half_rn(v);
    }
    if (i < BATCH * MDIM) { prior[i] = 0.f; post[i] = 0.f; }
}

__global__ void wsplit_kernel(const float* __restrict__ in,
                              __half* __restrict__ oh, __half* __restrict__ ol,
                              int K, int N) {
    int i = blockIdx.x * blockDim.x + threadIdx.x;
    if (i < K * N) {
        int k = i / N, n = i % N;
        wsplit_store(in[i], oh, ol, (size_t)n * K + k);
    }
}

__global__ void feat_a1_kernel(const float* __restrict__ y_t,
                               const float* __restrict__ F, const float* __restrict__ Hm,
                               const float* __restrict__ W1, const float* __restrict__ b1,
                               const float* __restrict__ post, float* __restrict__ prior,
                               float* __restrict__ dm1y_out, __half* __restrict__ a1) {
    __shared__ float feat[64][9];
    int tid = threadIdx.x;
    int b0 = blockIdx.x * 64;
    if (tid < 64) {
        int b = b0 + tid;
        float p[4], pr_old[4];
        #pragma unroll
        for (int m = 0; m < 4; m++) { p[m] = post[b*4+m]; pr_old[m] = prior[b*4+m]; }
        float pn[4];
        #pragma unroll
        for (int i = 0; i < 4; i++) {
            float s = 0.f;
            #pragma unroll
            for (int j = 0; j < 4; j++) s += __ldg(&F[i*4+j]) * p[j];
            pn[i] = s;
        }
        float my[2];
        #pragma unroll
        for (int i = 0; i < 2; i++) {
            float s = 0.f;
            #pragma unroll
            for (int j = 0; j < 4; j++) s += __ldg(&Hm[i*4+j]) * pn[j];
            my[i] = s;
        }
        float dy0 = y_t[b*2+0] - my[0];
        float dy1 = y_t[b*2+1] - my[1];
        dm1y_out[b*2+0] = dy0;
        dm1y_out[b*2+1] = dy1;
        float inv_y = rsqrtf(fmaxf(dy0*dy0 + dy1*dy1, 1e-12f));
        feat[tid][0] = dy0*inv_y; feat[tid][1] = dy1*inv_y;
        feat[tid][2] = dy0*inv_y; feat[tid][3] = dy1*inv_y;
        float d[4], s2 = 0.f;
        #pragma unroll
        for (int m = 0; m < 4; m++) { d[m] = p[m] - pr_old[m]; s2 += d[m]*d[m]; }
        float inv_x = rsqrtf(fmaxf(s2, 1e-12f));
        #pragma unroll
        for (int m = 0; m < 4; m++) feat[tid][4+m] = d[m]*inv_x;
        #pragma unroll
        for (int m = 0; m < 4; m++) prior[b*4+m] = pn[m];
    }
    __syncthreads();
    for (int idx = tid; idx < 64 * H1; idx += 256) {
        int r = idx / H1, c = idx % H1;
        float s = __ldg(&b1[c]);
        #pragma unroll
        for (int k = 0; k < 8; k++) s += feat[r][k] * __ldg(&W1[k*H1 + c]);
        a1[(size_t)(b0 + r) * H1 + c] = __float2half_rn(fmaxf(s, 0.f));
    }
}

// GRU gate combine, float2-vectorized (HID=200 -> 100 pairs per row)
__global__ void gru_gate_kernel(const float* __restrict__ Gx, const float* __restrict__ Gh,
                                const float* __restrict__ h_in, float* __restrict__ h_out,
                                __half* __restrict__ hnh) {
    int idx = blockIdx.x * blockDim.x + threadIdx.x;     // pair index
    if (idx >= BATCH * HID / 2) return;
    int b = idx / (HID / 2), jp = idx % (HID / 2);
    const float* gx = Gx + (size_t)b * 3 * HID;
    const float* gh = Gh + (size_t)b * 3 * HID;
    int j = jp * 2;
    float2 xz = *(const float2*)&gx[j];
    float2 hz = *(const float2*)&gh[j];
    float2 xr = *(const float2*)&gx[j + HID];
    float2 hr = *(const float2*)&gh[j + HID];
    float2 xh = *(const float2*)&gx[j + 2*HID];
    float2 hh = *(const float2*)&gh[j + 2*HID];
    float2 h  = *(const float2*)&h_in[(size_t)b * HID + j];
    float z0 = 1.f / (1.f + __expf(-(xz.x + hz.x)));
    float z1 = 1.f / (1.f + __expf(-(xz.y + hz.y)));
    float r0 = 1.f / (1.f + __expf(-(xr.x + hr.x)));
    float r1 = 1.f / (1.f + __expf(-(xr.y + hr.y)));
    float c0 = tanhf(xh.x + r0 * hh.x);
    float c1 = tanhf(xh.y + r1 * hh.y);
    float v0 = z0 * h.x + (1.f - z0) * c0;
    float v1 = z1 * h.y + (1.f - z1) * c1;
    *(float2*)&h_out[(size_t)b * HID + j] = make_float2(v0, v1);
    __half2 hv; hv.x = __float2half_rn(v0); hv.y = __float2half_rn(v1);
    *(__half2*)&hnh[(size_t)b * HID + j] = hv;
}

__global__ void out_kernel(const float* __restrict__ a2, const float* __restrict__ W3,
                           const float* __restrict__ b3, const float* __restrict__ dm1y,
                           const float* __restrict__ prior, float* __restrict__ post,
                           float* __restrict__ out_t) {
    int tid = threadIdx.x;
    int lane = tid & 7;
    int b = blockIdx.x * 32 + (tid >> 3);
    float kg[8];
    #pragma unroll
    for (int o = 0; o < 8; o++) kg[o] = 0.f;
    const float* arow = a2 + (size_t)b * H2;
    for (int k = lane; k < H2; k += 8) {
        float a = arow[k];
        float4 w0 = *(const float4*)(W3 + k*8);
        float4 w1 = *(const float4*)(W3 + k*8 + 4);
        kg[0] = fmaf(a, w0.x, kg[0]); kg[1] = fmaf(a, w0.y, kg[1]);
        kg[2] = fmaf(a, w0.z, kg[2]); kg[3] = fmaf(a, w0.w, kg[3]);
        kg[4] = fmaf(a, w1.x, kg[4]); kg[5] = fmaf(a, w1.y, kg[5]);
        kg[6] = fmaf(a, w1.z, kg[6]); kg[7] = fmaf(a, w1.w, kg[7]);
    }
    #pragma unroll
    for (int off = 4; off > 0; off >>= 1)
        #pragma unroll
        for (int o = 0; o < 8; o++)
            kg[o] += __shfl_down_sync(0xFFFFFFFFu, kg[o], off, 8);
    if (lane == 0) {
        float dy0 = dm1y[b*2+0], dy1 = dm1y[b*2+1];
        #pragma unroll
        for (int m = 0; m < 4; m++) {
            float k0 = kg[2*m]   + __ldg(&b3[2*m]);
            float k1 = kg[2*m+1] + __ldg(&b3[2*m+1]);
            float pv = prior[b*4+m] + k0*dy0 + k1*dy1;
            post[b*4+m] = pv;
            out_t[b*4+m] = pv;
        }
    }
}

// ---------------- launch ----------------------------------------------------
extern "C" void kernel_launch(void* const* d_in, const int* in_sizes, int n_in,
                              void* d_out, int out_size) {
    const float* y   = (const float*)d_in[0];
    const float* F   = (const float*)d_in[1];
    const float* Hm  = (const float*)d_in[2];
    const float* W1  = (const float*)d_in[3];
    const float* b1  = (const float*)d_in[4];
    const float* Wg  = (const float*)d_in[5];   // [480,600]
    const float* Ug  = (const float*)d_in[6];   // [200,600]
    const float* bg  = (const float*)d_in[7];   // [2,600]
    const float* W2  = (const float*)d_in[8];   // [200,320]
    const float* b2  = (const float*)d_in[9];
    const float* W3  = (const float*)d_in[10];
    const float* b3  = (const float*)d_in[11];
    const float* hn0 = (const float*)d_in[12];
    float* out = (float*)d_out;

    float *gx, *gh, *a2, *hn, *prior, *post, *dm1y;
    __half *a1, *hnh, *WgTh, *WgTl, *UgTh, *UgTl, *W2Th, *W2Tl;
    cudaGetSymbolAddress((void**)&gx,   g_gx);
    cudaGetSymbolAddress((void**)&gh,   g_gh);
    cudaGetSymbolAddress((void**)&a2,   g_a2);
    cudaGetSymbolAddress((void**)&hn,   g_hn);
    cudaGetSymbolAddress((void**)&prior,g_prior);
    cudaGetSymbolAddress((void**)&post, g_post);
    cudaGetSymbolAddress((void**)&dm1y, g_dm1y);
    cudaGetSymbolAddress((void**)&a1,   g_a1);
    cudaGetSymbolAddress((void**)&hnh,  g_hnh);
    cudaGetSymbolAddress((void**)&WgTh, g_WgTh);
    cudaGetSymbolAddress((void**)&WgTl, g_WgTl);
    cudaGetSymbolAddress((void**)&UgTh, g_UgTh);
    cudaGetSymbolAddress((void**)&UgTl, g_UgTl);
    cudaGetSymbolAddress((void**)&W2Th, g_W2Th);
    cudaGetSymbolAddress((void**)&W2Tl, g_W2Tl);

    const int SMEM = 2 * STAGE;     // 73728
    cudaFuncSetAttribute(gemm_dual,
                         cudaFuncAttributeMaxDynamicSharedMemorySize, SMEM);
    cudaFuncSetAttribute(gemm_single_relu,
                         cudaFuncAttributeMaxDynamicSharedMemorySize, SMEM);

    wsplit_kernel<<<(H1*3*HID + 255)/256, 256>>>(Wg, WgTh, WgTl, H1, 3*HID);
    wsplit_kernel<<<(HID*3*HID + 255)/256, 256>>>(Ug, UgTh, UgTl, HID, 3*HID);
    wsplit_kernel<<<(HID*H2 + 255)/256, 256>>>(W2, W2Th, W2Tl, HID, H2);
    init_kernel<<<(BATCH*HID + 255)/256, 256>>>(hn0, hn, hnh, prior, post);

    for (int t = 0; t < T_STEPS; t++) {
        const float* hin = hn + (size_t)(t & 1) * BATCH * HID;
        float* hout      = hn + (size_t)((t + 1) & 1) * BATCH * HID;

        feat_a1_kernel<<<BATCH/64, 256>>>(y + (size_t)t*BATCH*NDIM, F, Hm, W1, b1,
                                          post, prior, dm1y, a1);

        gemm_dual<<<dim3(10, 2 * (BATCH/128)), 256, SMEM>>>(
            a1,  WgTh, WgTl, bg,         gx,
            hnh, UgTh, UgTl, bg + 3*HID, gh);

        gru_gate_kernel<<<(BATCH*HID/2 + 255)/256, 256>>>(gx, gh, hin, hout, hnh);

        gemm_single_relu<<<dim3(5, BATCH/128), 256, SMEM>>>(
            hnh, W2Th, W2Tl, b2, a2, H2);

        out_kernel<<<BATCH/32, 256>>>(a2, W3, b3, dm1y, prior, post,
                                      out + (size_t)t*BATCH*MDIM);
    }
}

// round 14
// speedup vs baseline: 1.3535x; 1.0022x over previous
#include <cuda_runtime.h>
#include <cuda_fp16.h>
#include <cstdint>
#include <math.h>

#define T_STEPS 32
#define BATCH   8192
#define MDIM    4
#define NDIM    2
#define H1      480
#define HID     200
#define H2      320

// ---------------- scratch (device globals; no allocation allowed) -----------
__device__ float g_gx  [BATCH * 3 * HID];
__device__ float g_gh  [BATCH * 3 * HID];
__device__ float g_a2  [BATCH * H2];
__device__ float g_hn  [2 * BATCH * HID];
__device__ float g_prior[BATCH * MDIM];
__device__ float g_post [BATCH * MDIM];
__device__ float g_dm1y [BATCH * NDIM];
__device__ __half g_a1 [BATCH * H1];
__device__ __half g_hnh[BATCH * HID];
__device__ __half g_WgTh[3*HID*H1],  g_WgTl[3*HID*H1];
__device__ __half g_UgTh[3*HID*HID], g_UgTl[3*HID*HID];
__device__ __half g_W2Th[H2*HID],    g_W2Tl[H2*HID];

// ---------------- PTX helpers ------------------------------------------------
__device__ __forceinline__ uint32_t smem_u32(const void* p) {
    uint32_t a;
    asm("{ .reg .u64 t; cvta.to.shared.u64 t, %1; cvt.u32.u64 %0, t; }" : "=r"(a) : "l"(p));
    return a;
}
__device__ __forceinline__ void cp16(uint32_t dst, const void* src) {
    asm volatile("cp.async.cg.shared.global [%0], [%1], 16;" :: "r"(dst), "l"(src) : "memory");
}
__device__ __forceinline__ void sts_zero16(uint32_t addr) {
    asm volatile("st.shared.v4.b32 [%0], {%1,%1,%1,%1};" :: "r"(addr), "r"(0) : "memory");
}
__device__ __forceinline__ void ldsm4(uint32_t* r, uint32_t addr) {
    asm volatile("ldmatrix.sync.aligned.m8n8.x4.shared.b16 {%0,%1,%2,%3}, [%4];"
                 : "=r"(r[0]), "=r"(r[1]), "=r"(r[2]), "=r"(r[3]) : "r"(addr));
}
__device__ __forceinline__ void mma16816(float* c, const uint32_t* a, uint32_t b0, uint32_t b1) {
    asm volatile("mma.sync.aligned.m16n8k16.row.col.f32.f16.f16.f32 "
                 "{%0,%1,%2,%3}, {%4,%5,%6,%7}, {%8,%9}, {%0,%1,%2,%3};"
                 : "+f"(c[0]), "+f"(c[1]), "+f"(c[2]), "+f"(c[3])
                 : "r"(a[0]), "r"(a[1]), "r"(a[2]), "r"(a[3]), "r"(b0), "r"(b1));
}

// ---------------- split-fp16 HMMA GEMM core ----------------------------------
// C[128 x BN] = A[M x K] @ (Bh+Bl)^T[N x K] + bias, fp32 out. BN = 16*NF.
// BK=64, 256 threads, 8 warps (4m x 2n), warp tile 32 x (8*NF), 2-stage cp.async.
// K compile-time: tail chunk trims both stage-fill and MMA steps.
#define ROWB   144                    // 128B data + 16B pad (conflict-free ldmatrix)
#define A_PL   (128 * ROWB)           // 18432

template<int K, int NF, bool RELU>
__device__ __forceinline__ void gemm_body(
        const __half* __restrict__ A,
        const __half* __restrict__ Bh, const __half* __restrict__ Bl,
        const float* __restrict__ bias, float* __restrict__ C,
        int Ncols, int bm, int bn, uint32_t s0) {
    constexpr int BN       = 16 * NF;
    constexpr int B_PL     = BN * ROWB;
    constexpr int STG      = A_PL + 2 * B_PL;
    constexpr int NC       = (K + 63) / 64;
    constexpr int TAIL     = K % 64;                      // 32 for 480, 8 for 200
    constexpr int TAIL_NKS = TAIL ? (TAIL + 15) / 16 : 4;
    constexpr int TAIL_CH  = TAIL ? TAIL_NKS * 2 : 8;

    const int tid  = threadIdx.x;
    const int lane = tid & 31, wid = tid >> 5;
    const int wm = (wid & 3) * 32;
    const int wn = (wid >> 2) * (8 * NF);

    float acc[2][NF][4];
    #pragma unroll
    for (int i = 0; i < 2; i++)
        #pragma unroll
        for (int j = 0; j < NF; j++)
            #pragma unroll
            for (int k = 0; k < 4; k++) acc[i][j][k] = 0.f;

    auto load_stage = [&](int s) {
        uint32_t base = s0 + (uint32_t)(s & 1) * STG;
        int k0 = s * 64;
        const bool last = TAIL && (s == NC - 1);
        const int kcc   = last ? TAIL : 64;
        const int chlim = last ? TAIL_CH : 8;
        #pragma unroll
        for (int it = 0; it < 4; it++) {             // A: 128 rows x 8 chunks
            int idx = tid + it * 256;
            int r = idx >> 3, ch = idx & 7;
            if (ch < chlim) {
                uint32_t dst = base + (uint32_t)r * ROWB + (uint32_t)ch * 16;
                if (ch * 8 < kcc)
                    cp16(dst, A + (size_t)(bm + r) * K + k0 + ch * 8);
                else
                    sts_zero16(dst);
            }
        }
        #pragma unroll
        for (int it = 0; it < BN / 16; it++) {       // B: 2 planes x BN rows x 8 chunks
            int idx = tid + it * 256;                //    = 16*BN slots -> BN/16 iters
            int plane = idx / (BN * 8);
            int r = (idx >> 3) & (BN - 1);
            int ch = idx & 7;
            if (ch < chlim) {
                uint32_t dst = base + A_PL + (uint32_t)plane * B_PL
                             + (uint32_t)r * ROWB + (uint32_t)ch * 16;
                if ((bn + r) < Ncols && ch * 8 < kcc)
                    cp16(dst, (plane ? Bl : Bh) + (size_t)(bn + r) * K + k0 + ch * 8);
                else
                    sts_zero16(dst);
            }
        }
        asm volatile("cp.async.commit_group;" ::: "memory");
    };

    load_stage(0);

    const uint32_t a_lrow = (uint32_t)(lane & 15) * ROWB + (uint32_t)(lane >> 4) * 16;
    const uint32_t b_lrow = (uint32_t)((lane & 7) + ((lane >> 3) & 1) * 8) * ROWB
                          + (uint32_t)(lane >> 4) * 16;

    #pragma unroll
    for (int i = 0; i < NC; i++) {
        if (i + 1 < NC) {
            load_stage(i + 1);
            asm volatile("cp.async.wait_group 1;" ::: "memory");
        } else {
            asm volatile("cp.async.wait_group 0;" ::: "memory");
        }
        __syncthreads();

        uint32_t base = s0 + (uint32_t)(i & 1) * STG;
        uint32_t sA = base, sB = base + A_PL;

        const int nks = (TAIL && i == NC - 1) ? TAIL_NKS : 4;
        #pragma unroll
        for (int ks = 0; ks < 4; ks++) {
            if (ks >= nks) break;
            uint32_t koff = (uint32_t)ks * 32;       // 16 halves = 32B
            uint32_t a[2][4];
            #pragma unroll
            for (int fm = 0; fm < 2; fm++)
                ldsm4(a[fm], sA + (uint32_t)(wm + fm * 16) * ROWB + koff + a_lrow);
            #pragma unroll
            for (int plane = 0; plane < 2; plane++) {
                uint32_t bf[NF / 2][4];
                #pragma unroll
                for (int nb = 0; nb < NF / 2; nb++)
                    ldsm4(bf[nb], sB + (uint32_t)plane * B_PL
                                  + (uint32_t)(wn + nb * 16) * ROWB + koff + b_lrow);
                #pragma unroll
                for (int fm = 0; fm < 2; fm++)
                    #pragma unroll
                    for (int j = 0; j < NF; j++)
                        mma16816(acc[fm][j], a[fm], bf[j >> 1][j & 1], bf[j >> 1][(j & 1) + 2]);
            }
        }
        __syncthreads();
    }

    const int qid = lane >> 2, qt = lane & 3;
    #pragma unroll
    for (int fm = 0; fm < 2; fm++) {
        int row = bm + wm + fm * 16 + qid;
        #pragma unroll
        for (int j = 0; j < NF; j++) {
            int col = bn + wn + j * 8 + qt * 2;
            if (col >= Ncols) continue;
            float b0 = __ldg(&bias[col]), b1 = __ldg(&bias[col + 1]);
            float2 v0 = make_float2(acc[fm][j][0] + b0, acc[fm][j][1] + b1);
            float2 v1 = make_float2(acc[fm][j][2] + b0, acc[fm][j][3] + b1);
            if (RELU) {
                v0.x = fmaxf(v0.x, 0.f); v0.y = fmaxf(v0.y, 0.f);
                v1.x = fmaxf(v1.x, 0.f); v1.y = fmaxf(v1.y, 0.f);
            }
            *(float2*)&C[(size_t)row * Ncols + col]       = v0;
            *(float2*)&C[(size_t)(row + 8) * Ncols + col] = v1;
        }
    }
}

// merged GEMM1 (a1@Wg -> gx, K=480) + GEMM2 (hnh@Ug -> gh, K=200), NF=8 (BN=128)
__global__ __launch_bounds__(256, 2)
void gemm_dual(const __half* __restrict__ A1, const __half* __restrict__ Bh1,
               const __half* __restrict__ Bl1, const float* __restrict__ bias1,
               float* __restrict__ C1,
               const __half* __restrict__ A2, const __half* __restrict__ Bh2,
               const __half* __restrict__ Bl2, const float* __restrict__ bias2,
               float* __restrict__ C2) {
    extern __shared__ char smem[];
    const uint32_t s0 = smem_u32(smem);
    const bool second = blockIdx.y >= (BATCH / 128);
    const int bm = (blockIdx.y & (BATCH / 128 - 1)) * 128;
    const int bn = blockIdx.x * 128;
    if (!second)
        gemm_body<H1,  8, false>(A1, Bh1, Bl1, bias1, C1, 3 * HID, bm, bn, s0);
    else
        gemm_body<HID, 8, false>(A2, Bh2, Bl2, bias2, C2, 3 * HID, bm, bn, s0);
}

// GEMM3: hnh@W2 -> a2, K=200, relu, NF=4 (BN=64, exact tiling)
__global__ __launch_bounds__(256, 3)
void gemm_single_relu(const __half* __restrict__ A, const __half* __restrict__ Bh,
                      const __half* __restrict__ Bl, const float* __restrict__ bias,
                      float* __restrict__ C, int Ncols) {
    extern __shared__ char smem[];
    gemm_body<HID, 4, true>(A, Bh, Bl, bias, C, Ncols,
                            blockIdx.y * 128, blockIdx.x * 64, smem_u32(smem));
}

// ---------------- small kernels ---------------------------------------------
__device__ __forceinline__ void wsplit_store(float v, __half* hi, __half* lo, size_t idx) {
    __half h = __float2half_rn(v);
    hi[idx] = h;
    lo[idx] = __float2half_rn(v - __half2float(h));
}

__global__ void init_kernel(const float* __restrict__ hn0, float* __restrict__ hn,
                            __half* __restrict__ hnh,
                            float* __restrict__ prior, float* __restrict__ post) {
    int i = blockIdx.x * blockDim.x + threadIdx.x;
    if (i < BATCH * HID) {
        float v = hn0[i];
        hn[i] = v;
        hnh[i] = __float2half_rn(v);
    }
    if (i < BATCH * MDIM) { prior[i] = 0.f; post[i] = 0.f; }
}

__global__ void wsplit_kernel(const float* __restrict__ in,
                              __half* __restrict__ oh, __half* __restrict__ ol,
                              int K, int N) {
    int i = blockIdx.x * blockDim.x + threadIdx.x;
    if (i < K * N) {
        int k = i / N, n = i % N;
        wsplit_store(in[i], oh, ol, (size_t)n * K + k);
    }
}

__global__ void feat_a1_kernel(const float* __restrict__ y_t,
                               const float* __restrict__ F, const float* __restrict__ Hm,
                               const float* __restrict__ W1, const float* __restrict__ b1,
                               const float* __restrict__ post, float* __restrict__ prior,
                               float* __restrict__ dm1y_out, __half* __restrict__ a1) {
    __shared__ float feat[64][9];
    int tid = threadIdx.x;
    int b0 = blockIdx.x * 64;
    if (tid < 64) {
        int b = b0 + tid;
        float p[4], pr_old[4];
        #pragma unroll
        for (int m = 0; m < 4; m++) { p[m] = post[b*4+m]; pr_old[m] = prior[b*4+m]; }
        float pn[4];
        #pragma unroll
        for (int i = 0; i < 4; i++) {
            float s = 0.f;
            #pragma unroll
            for (int j = 0; j < 4; j++) s += __ldg(&F[i*4+j]) * p[j];
            pn[i] = s;
        }
        float my[2];
        #pragma unroll
        for (int i = 0; i < 2; i++) {
            float s = 0.f;
            #pragma unroll
            for (int j = 0; j < 4; j++) s += __ldg(&Hm[i*4+j]) * pn[j];
            my[i] = s;
        }
        float dy0 = y_t[b*2+0] - my[0];
        float dy1 = y_t[b*2+1] - my[1];
        dm1y_out[b*2+0] = dy0;
        dm1y_out[b*2+1] = dy1;
        float inv_y = rsqrtf(fmaxf(dy0*dy0 + dy1*dy1, 1e-12f));
        feat[tid][0] = dy0*inv_y; feat[tid][1] = dy1*inv_y;
        feat[tid][2] = dy0*inv_y; feat[tid][3] = dy1*inv_y;
        float d[4], s2 = 0.f;
        #pragma unroll
        for (int m = 0; m < 4; m++) { d[m] = p[m] - pr_old[m]; s2 += d[m]*d[m]; }
        float inv_x = rsqrtf(fmaxf(s2, 1e-12f));
        #pragma unroll
        for (int m = 0; m < 4; m++) feat[tid][4+m] = d[m]*inv_x;
        #pragma unroll
        for (int m = 0; m < 4; m++) prior[b*4+m] = pn[m];
    }
    __syncthreads();
    for (int idx = tid; idx < 64 * H1; idx += 256) {
        int r = idx / H1, c = idx % H1;
        float s = __ldg(&b1[c]);
        #pragma unroll
        for (int k = 0; k < 8; k++) s += feat[r][k] * __ldg(&W1[k*H1 + c]);
        a1[(size_t)(b0 + r) * H1 + c] = __float2half_rn(fmaxf(s, 0.f));
    }
}

// GRU gate combine, float2-vectorized (HID=200 -> 100 pairs per row)
__global__ void gru_gate_kernel(const float* __restrict__ Gx, const float* __restrict__ Gh,
                                const float* __restrict__ h_in, float* __restrict__ h_out,
                                __half* __restrict__ hnh) {
    int idx = blockIdx.x * blockDim.x + threadIdx.x;     // pair index
    if (idx >= BATCH * HID / 2) return;
    int b = idx / (HID / 2), jp = idx % (HID / 2);
    const float* gx = Gx + (size_t)b * 3 * HID;
    const float* gh = Gh + (size_t)b * 3 * HID;
    int j = jp * 2;
    float2 xz = *(const float2*)&gx[j];
    float2 hz = *(const float2*)&gh[j];
    float2 xr = *(const float2*)&gx[j + HID];
    float2 hr = *(const float2*)&gh[j + HID];
    float2 xh = *(const float2*)&gx[j + 2*HID];
    float2 hh = *(const float2*)&gh[j + 2*HID];
    float2 h  = *(const float2*)&h_in[(size_t)b * HID + j];
    float z0 = 1.f / (1.f + __expf(-(xz.x + hz.x)));
    float z1 = 1.f / (1.f + __expf(-(xz.y + hz.y)));
    float r0 = 1.f / (1.f + __expf(-(xr.x + hr.x)));
    float r1 = 1.f / (1.f + __expf(-(xr.y + hr.y)));
    float c0 = tanhf(xh.x + r0 * hh.x);
    float c1 = tanhf(xh.y + r1 * hh.y);
    float v0 = z0 * h.x + (1.f - z0) * c0;
    float v1 = z1 * h.y + (1.f - z1) * c1;
    *(float2*)&h_out[(size_t)b * HID + j] = make_float2(v0, v1);
    __half2 hv; hv.x = __float2half_rn(v0); hv.y = __float2half_rn(v1);
    *(__half2*)&hnh[(size_t)b * HID + j] = hv;
}

__global__ void out_kernel(const float* __restrict__ a2, const float* __restrict__ W3,
                           const float* __restrict__ b3, const float* __restrict__ dm1y,
                           const float* __restrict__ prior, float* __restrict__ post,
                           float* __restrict__ out_t) {
    int tid = threadIdx.x;
    int lane = tid & 7;
    int b = blockIdx.x * 32 + (tid >> 3);
    float kg[8];
    #pragma unroll
    for (int o = 0; o < 8; o++) kg[o] = 0.f;
    const float* arow = a2 + (size_t)b * H2;
    for (int k = lane; k < H2; k += 8) {
        float a = arow[k];
        float4 w0 = *(const float4*)(W3 + k*8);
        float4 w1 = *(const float4*)(W3 + k*8 + 4);
        kg[0] = fmaf(a, w0.x, kg[0]); kg[1] = fmaf(a, w0.y, kg[1]);
        kg[2] = fmaf(a, w0.z, kg[2]); kg[3] = fmaf(a, w0.w, kg[3]);
        kg[4] = fmaf(a, w1.x, kg[4]); kg[5] = fmaf(a, w1.y, kg[5]);
        kg[6] = fmaf(a, w1.z, kg[6]); kg[7] = fmaf(a, w1.w, kg[7]);
    }
    #pragma unroll
    for (int off = 4; off > 0; off >>= 1)
        #pragma unroll
        for (int o = 0; o < 8; o++)
            kg[o] += __shfl_down_sync(0xFFFFFFFFu, kg[o], off, 8);
    if (lane == 0) {
        float dy0 = dm1y[b*2+0], dy1 = dm1y[b*2+1];
        #pragma unroll
        for (int m = 0; m < 4; m++) {
            float k0 = kg[2*m]   + __ldg(&b3[2*m]);
            float k1 = kg[2*m+1] + __ldg(&b3[2*m+1]);
            float pv = prior[b*4+m] + k0*dy0 + k1*dy1;
            post[b*4+m] = pv;
            out_t[b*4+m] = pv;
        }
    }
}

// ---------------- launch ----------------------------------------------------
extern "C" void kernel_launch(void* const* d_in, const int* in_sizes, int n_in,
                              void* d_out, int out_size) {
    const float* y   = (const float*)d_in[0];
    const float* F   = (const float*)d_in[1];
    const float* Hm  = (const float*)d_in[2];
    const float* W1  = (const float*)d_in[3];
    const float* b1  = (const float*)d_in[4];
    const float* Wg  = (const float*)d_in[5];   // [480,600]
    const float* Ug  = (const float*)d_in[6];   // [200,600]
    const float* bg  = (const float*)d_in[7];   // [2,600]
    const float* W2  = (const float*)d_in[8];   // [200,320]
    const float* b2  = (const float*)d_in[9];
    const float* W3  = (const float*)d_in[10];
    const float* b3  = (const float*)d_in[11];
    const float* hn0 = (const float*)d_in[12];
    float* out = (float*)d_out;

    float *gx, *gh, *a2, *hn, *prior, *post, *dm1y;
    __half *a1, *hnh, *WgTh, *WgTl, *UgTh, *UgTl, *W2Th, *W2Tl;
    cudaGetSymbolAddress((void**)&gx,   g_gx);
    cudaGetSymbolAddress((void**)&gh,   g_gh);
    cudaGetSymbolAddress((void**)&a2,   g_a2);
    cudaGetSymbolAddress((void**)&hn,   g_hn);
    cudaGetSymbolAddress((void**)&prior,g_prior);
    cudaGetSymbolAddress((void**)&post, g_post);
    cudaGetSymbolAddress((void**)&dm1y, g_dm1y);
    cudaGetSymbolAddress((void**)&a1,   g_a1);
    cudaGetSymbolAddress((void**)&hnh,  g_hnh);
    cudaGetSymbolAddress((void**)&WgTh, g_WgTh);
    cudaGetSymbolAddress((void**)&WgTl, g_WgTl);
    cudaGetSymbolAddress((void**)&UgTh, g_UgTh);
    cudaGetSymbolAddress((void**)&UgTl, g_UgTl);
    cudaGetSymbolAddress((void**)&W2Th, g_W2Th);
    cudaGetSymbolAddress((void**)&W2Tl, g_W2Tl);

    const int SMEM8 = 2 * (A_PL + 2 * 128 * ROWB);   // 110592 (NF=8)
    const int SMEM4 = 2 * (A_PL + 2 * 64 * ROWB);    // 73728  (NF=4)
    cudaFuncSetAttribute(gemm_dual,
                         cudaFuncAttributeMaxDynamicSharedMemorySize, SMEM8);
    cudaFuncSetAttribute(gemm_single_relu,
                         cudaFuncAttributeMaxDynamicSharedMemorySize, SMEM4);

    wsplit_kernel<<<(H1*3*HID + 255)/256, 256>>>(Wg, WgTh, WgTl, H1, 3*HID);
    wsplit_kernel<<<(HID*3*HID + 255)/256, 256>>>(Ug, UgTh, UgTl, HID, 3*HID);
    wsplit_kernel<<<(HID*H2 + 255)/256, 256>>>(W2, W2Th, W2Tl, HID, H2);
    init_kernel<<<(BATCH*HID + 255)/256, 256>>>(hn0, hn, hnh, prior, post);

    for (int t = 0; t < T_STEPS; t++) {
        const float* hin = hn + (size_t)(t & 1) * BATCH * HID;
        float* hout      = hn + (size_t)((t + 1) & 1) * BATCH * HID;

        feat_a1_kernel<<<BATCH/64, 256>>>(y + (size_t)t*BATCH*NDIM, F, Hm, W1, b1,
                                          post, prior, dm1y, a1);

        gemm_dual<<<dim3(5, 2 * (BATCH/128)), 256, SMEM8>>>(
            a1,  WgTh, WgTl, bg,         gx,
            hnh, UgTh, UgTl, bg + 3*HID, gh);

        gru_gate_kernel<<<(BATCH*HID/2 + 255)/256, 256>>>(gx, gh, hin, hout, hnh);

        gemm_single_relu<<<dim3(5, BATCH/128), 256, SMEM4>>>(
            hnh, W2Th, W2Tl, b2, a2, H2);

        out_kernel<<<BATCH/32, 256>>>(a2, W3, b3, dm1y, prior, post,
                                      out + (size_t)t*BATCH*MDIM);
    }
}

// round 15
// speedup vs baseline: 1.4440x; 1.0669x over previous
#include <cuda_runtime.h>
#include <cuda_fp16.h>
#include <cstdint>
#include <math.h>

#define T_STEPS 32
#define BATCH   8192
#define MDIM    4
#define NDIM    2
#define H1      480
#define HID     200
#define H2      320

// ---------------- scratch (device globals; no allocation allowed) -----------
__device__ float g_gx  [BATCH * 3 * HID];
__device__ float g_gh  [BATCH * 3 * HID];
__device__ float g_a2  [BATCH * H2];
__device__ float g_hn  [2 * BATCH * HID];
__device__ float g_prior[BATCH * MDIM];
__device__ float g_post [BATCH * MDIM];
__device__ float g_dm1y [BATCH * NDIM];
__device__ __half g_a1 [BATCH * H1];
__device__ __half g_hnh[BATCH * HID];
__device__ __half g_WgTh[3*HID*H1],  g_WgTl[3*HID*H1];
__device__ __half g_UgTh[3*HID*HID], g_UgTl[3*HID*HID];
__device__ __half g_W2Th[H2*HID],    g_W2Tl[H2*HID];

// ---------------- PTX helpers ------------------------------------------------
__device__ __forceinline__ uint32_t smem_u32(const void* p) {
    uint32_t a;
    asm("{ .reg .u64 t; cvta.to.shared.u64 t, %1; cvt.u32.u64 %0, t; }" : "=r"(a) : "l"(p));
    return a;
}
__device__ __forceinline__ void cp16(uint32_t dst, const void* src) {
    asm volatile("cp.async.cg.shared.global [%0], [%1], 16;" :: "r"(dst), "l"(src) : "memory");
}
__device__ __forceinline__ void sts_zero16(uint32_t addr) {
    asm volatile("st.shared.v4.b32 [%0], {%1,%1,%1,%1};" :: "r"(addr), "r"(0) : "memory");
}
__device__ __forceinline__ void ldsm4(uint32_t* r, uint32_t addr) {
    asm volatile("ldmatrix.sync.aligned.m8n8.x4.shared.b16 {%0,%1,%2,%3}, [%4];"
                 : "=r"(r[0]), "=r"(r[1]), "=r"(r[2]), "=r"(r[3]) : "r"(addr));
}
__device__ __forceinline__ void mma16816(float* c, const uint32_t* a, uint32_t b0, uint32_t b1) {
    asm volatile("mma.sync.aligned.m16n8k16.row.col.f32.f16.f16.f32 "
                 "{%0,%1,%2,%3}, {%4,%5,%6,%7}, {%8,%9}, {%0,%1,%2,%3};"
                 : "+f"(c[0]), "+f"(c[1]), "+f"(c[2]), "+f"(c[3])
                 : "r"(a[0]), "r"(a[1]), "r"(a[2]), "r"(a[3]), "r"(b0), "r"(b1));
}

// ---------------- split-fp16 HMMA GEMM core ----------------------------------
// C[128 x BN] = A[M x K] @ (Bh+Bl)^T[N x K] + bias, fp32 out. BN = 16*NF.
// BK=64, 256 threads, 8 warps (4m x 2n), warp tile 32 x (8*NF), 2-stage cp.async.
#define ROWB   144                    // 128B data + 16B pad (conflict-free ldmatrix)
#define A_PL   (128 * ROWB)           // 18432

template<int K, int NF, bool RELU>
__device__ __forceinline__ void gemm_body(
        const __half* __restrict__ A,
        const __half* __restrict__ Bh, const __half* __restrict__ Bl,
        const float* __restrict__ bias, float* __restrict__ C,
        int Ncols, int bm, int bn, uint32_t s0) {
    constexpr int BN       = 16 * NF;
    constexpr int B_PL     = BN * ROWB;
    constexpr int STG      = A_PL + 2 * B_PL;
    constexpr int NC       = (K + 63) / 64;
    constexpr int TAIL     = K % 64;
    constexpr int TAIL_NKS = TAIL ? (TAIL + 15) / 16 : 4;
    constexpr int TAIL_CH  = TAIL ? TAIL_NKS * 2 : 8;

    const int tid  = threadIdx.x;
    const int lane = tid & 31, wid = tid >> 5;
    const int wm = (wid & 3) * 32;
    const int wn = (wid >> 2) * (8 * NF);

    float acc[2][NF][4];
    #pragma unroll
    for (int i = 0; i < 2; i++)
        #pragma unroll
        for (int j = 0; j < NF; j++)
            #pragma unroll
            for (int k = 0; k < 4; k++) acc[i][j][k] = 0.f;

    auto load_stage = [&](int s) {
        uint32_t base = s0 + (uint32_t)(s & 1) * STG;
        int k0 = s * 64;
        const bool last = TAIL && (s == NC - 1);
        const int kcc   = last ? TAIL : 64;
        const int chlim = last ? TAIL_CH : 8;
        #pragma unroll
        for (int it = 0; it < 4; it++) {             // A: 128 rows x 8 chunks
            int idx = tid + it * 256;
            int r = idx >> 3, ch = idx & 7;
            if (ch < chlim) {
                uint32_t dst = base + (uint32_t)r * ROWB + (uint32_t)ch * 16;
                if (ch * 8 < kcc)
                    cp16(dst, A + (size_t)(bm + r) * K + k0 + ch * 8);
                else
                    sts_zero16(dst);
            }
        }
        #pragma unroll
        for (int it = 0; it < BN / 16; it++) {       // B: 2 planes x BN rows x 8 chunks
            int idx = tid + it * 256;
            int plane = idx / (BN * 8);
            int r = (idx >> 3) & (BN - 1);
            int ch = idx & 7;
            if (ch < chlim) {
                uint32_t dst = base + A_PL + (uint32_t)plane * B_PL
                             + (uint32_t)r * ROWB + (uint32_t)ch * 16;
                if ((bn + r) < Ncols && ch * 8 < kcc)
                    cp16(dst, (plane ? Bl : Bh) + (size_t)(bn + r) * K + k0 + ch * 8);
                else
                    sts_zero16(dst);
            }
        }
        asm volatile("cp.async.commit_group;" ::: "memory");
    };

    load_stage(0);

    const uint32_t a_lrow = (uint32_t)(lane & 15) * ROWB + (uint32_t)(lane >> 4) * 16;
    const uint32_t b_lrow = (uint32_t)((lane & 7) + ((lane >> 3) & 1) * 8) * ROWB
                          + (uint32_t)(lane >> 4) * 16;

    #pragma unroll
    for (int i = 0; i < NC; i++) {
        if (i + 1 < NC) {
            load_stage(i + 1);
            asm volatile("cp.async.wait_group 1;" ::: "memory");
        } else {
            asm volatile("cp.async.wait_group 0;" ::: "memory");
        }
        __syncthreads();

        uint32_t base = s0 + (uint32_t)(i & 1) * STG;
        uint32_t sA = base, sB = base + A_PL;

        const int nks = (TAIL && i == NC - 1) ? TAIL_NKS : 4;
        #pragma unroll
        for (int ks = 0; ks < 4; ks++) {
            if (ks >= nks) break;
            uint32_t koff = (uint32_t)ks * 32;       // 16 halves = 32B
            uint32_t a[2][4];
            #pragma unroll
            for (int fm = 0; fm < 2; fm++)
                ldsm4(a[fm], sA + (uint32_t)(wm + fm * 16) * ROWB + koff + a_lrow);
            #pragma unroll
            for (int plane = 0; plane < 2; plane++) {
                uint32_t bf[NF / 2][4];
                #pragma unroll
                for (int nb = 0; nb < NF / 2; nb++)
                    ldsm4(bf[nb], sB + (uint32_t)plane * B_PL
                                  + (uint32_t)(wn + nb * 16) * ROWB + koff + b_lrow);
                #pragma unroll
                for (int fm = 0; fm < 2; fm++)
                    #pragma unroll
                    for (int j = 0; j < NF; j++)
                        mma16816(acc[fm][j], a[fm], bf[j >> 1][j & 1], bf[j >> 1][(j & 1) + 2]);
            }
        }
        __syncthreads();
    }

    const int qid = lane >> 2, qt = lane & 3;
    #pragma unroll
    for (int fm = 0; fm < 2; fm++) {
        int row = bm + wm + fm * 16 + qid;
        #pragma unroll
        for (int j = 0; j < NF; j++) {
            int col = bn + wn + j * 8 + qt * 2;
            if (col >= Ncols) continue;
            float b0 = __ldg(&bias[col]), b1 = __ldg(&bias[col + 1]);
            float2 v0 = make_float2(acc[fm][j][0] + b0, acc[fm][j][1] + b1);
            float2 v1 = make_float2(acc[fm][j][2] + b0, acc[fm][j][3] + b1);
            if (RELU) {
                v0.x = fmaxf(v0.x, 0.f); v0.y = fmaxf(v0.y, 0.f);
                v1.x = fmaxf(v1.x, 0.f); v1.y = fmaxf(v1.y, 0.f);
            }
            *(float2*)&C[(size_t)row * Ncols + col]       = v0;
            *(float2*)&C[(size_t)(row + 8) * Ncols + col] = v1;
        }
    }
}

// merged GEMM1 (a1@Wg -> gx, K=480) + GEMM2 (hnh@Ug -> gh, K=200), NF=8 (BN=128)
__global__ __launch_bounds__(256, 2)
void gemm_dual(const __half* __restrict__ A1, const __half* __restrict__ Bh1,
               const __half* __restrict__ Bl1, const float* __restrict__ bias1,
               float* __restrict__ C1,
               const __half* __restrict__ A2, const __half* __restrict__ Bh2,
               const __half* __restrict__ Bl2, const float* __restrict__ bias2,
               float* __restrict__ C2) {
    extern __shared__ char smem[];
    const uint32_t s0 = smem_u32(smem);
    const bool second = blockIdx.y >= (BATCH / 128);
    const int bm = (blockIdx.y & (BATCH / 128 - 1)) * 128;
    const int bn = blockIdx.x * 128;
    if (!second)
        gemm_body<H1,  8, false>(A1, Bh1, Bl1, bias1, C1, 3 * HID, bm, bn, s0);
    else
        gemm_body<HID, 8, false>(A2, Bh2, Bl2, bias2, C2, 3 * HID, bm, bn, s0);
}

// GEMM3: hnh@W2 -> a2, K=200, relu, NF=4 (BN=64, exact tiling)
__global__ __launch_bounds__(256, 3)
void gemm_single_relu(const __half* __restrict__ A, const __half* __restrict__ Bh,
                      const __half* __restrict__ Bl, const float* __restrict__ bias,
                      float* __restrict__ C, int Ncols) {
    extern __shared__ char smem[];
    gemm_body<HID, 4, true>(A, Bh, Bl, bias, C, Ncols,
                            blockIdx.y * 128, blockIdx.x * 64, smem_u32(smem));
}

// ---------------- small kernels ---------------------------------------------
__device__ __forceinline__ void wsplit_store(float v, __half* hi, __half* lo, size_t idx) {
    __half h = __float2half_rn(v);
    hi[idx] = h;
    lo[idx] = __float2half_rn(v - __half2float(h));
}

__global__ void init_kernel(const float* __restrict__ hn0, float* __restrict__ hn,
                            __half* __restrict__ hnh,
                            float* __restrict__ prior, float* __restrict__ post) {
    int i = blockIdx.x * blockDim.x + threadIdx.x;
    if (i < BATCH * HID) {
        float v = hn0[i];
        hn[i] = v;
        hnh[i] = __float2half_rn(v);
    }
    if (i < BATCH * MDIM) { prior[i] = 0.f; post[i] = 0.f; }
}

__global__ void wsplit_kernel(const float* __restrict__ in,
                              __half* __restrict__ oh, __half* __restrict__ ol,
                              int K, int N) {
    int i = blockIdx.x * blockDim.x + threadIdx.x;
    if (i < K * N) {
        int k = i / N, n = i % N;
        wsplit_store(in[i], oh, ol, (size_t)n * K + k);
    }
}

// features + a1 for 64 batch rows per block; NT = block size
template<int NT>
__device__ __forceinline__ void feat_a1_body(
        const float* __restrict__ y_t,
        const float* __restrict__ F, const float* __restrict__ Hm,
        const float* __restrict__ W1, const float* __restrict__ b1,
        const float* __restrict__ post, float* __restrict__ prior,
        float* __restrict__ dm1y_out, __half* __restrict__ a1,
        float (*feat)[9], int tid, int b0) {
    if (tid < 64) {
        int b = b0 + tid;
        float p[4], pr_old[4];
        #pragma unroll
        for (int m = 0; m < 4; m++) { p[m] = post[b*4+m]; pr_old[m] = prior[b*4+m]; }
        float pn[4];
        #pragma unroll
        for (int i = 0; i < 4; i++) {
            float s = 0.f;
            #pragma unroll
            for (int j = 0; j < 4; j++) s += __ldg(&F[i*4+j]) * p[j];
            pn[i] = s;
        }
        float my[2];
        #pragma unroll
        for (int i = 0; i < 2; i++) {
            float s = 0.f;
            #pragma unroll
            for (int j = 0; j < 4; j++) s += __ldg(&Hm[i*4+j]) * pn[j];
            my[i] = s;
        }
        float dy0 = y_t[b*2+0] - my[0];
        float dy1 = y_t[b*2+1] - my[1];
        dm1y_out[b*2+0] = dy0;
        dm1y_out[b*2+1] = dy1;
        float inv_y = rsqrtf(fmaxf(dy0*dy0 + dy1*dy1, 1e-12f));
        feat[tid][0] = dy0*inv_y; feat[tid][1] = dy1*inv_y;
        feat[tid][2] = dy0*inv_y; feat[tid][3] = dy1*inv_y;
        float d[4], s2 = 0.f;
        #pragma unroll
        for (int m = 0; m < 4; m++) { d[m] = p[m] - pr_old[m]; s2 += d[m]*d[m]; }
        float inv_x = rsqrtf(fmaxf(s2, 1e-12f));
        #pragma unroll
        for (int m = 0; m < 4; m++) feat[tid][4+m] = d[m]*inv_x;
        #pragma unroll
        for (int m = 0; m < 4; m++) prior[b*4+m] = pn[m];
    }
    __syncthreads();
    for (int idx = tid; idx < 64 * H1; idx += NT) {
        int r = idx / H1, c = idx % H1;
        float s = __ldg(&b1[c]);
        #pragma unroll
        for (int k = 0; k < 8; k++) s += feat[r][k] * __ldg(&W1[k*H1 + c]);
        a1[(size_t)(b0 + r) * H1 + c] = __float2half_rn(fmaxf(s, 0.f));
    }
}

__global__ void feat_a1_kernel(const float* __restrict__ y_t,
                               const float* __restrict__ F, const float* __restrict__ Hm,
                               const float* __restrict__ W1, const float* __restrict__ b1,
                               const float* __restrict__ post, float* __restrict__ prior,
                               float* __restrict__ dm1y_out, __half* __restrict__ a1) {
    __shared__ float feat[64][9];
    feat_a1_body<256>(y_t, F, Hm, W1, b1, post, prior, dm1y_out, a1,
                      feat, threadIdx.x, blockIdx.x * 64);
}

// posterior(t) + features/a1(t+1) fused; 512 threads, 64 batch rows per block.
// phase 1 uses 8-lane teams (identical shape/order to out_kernel -> bit-identical).
__global__ __launch_bounds__(512)
void post_feat_kernel(const float* __restrict__ a2, const float* __restrict__ W3,
                      const float* __restrict__ b3,
                      const float* __restrict__ y_next,
                      const float* __restrict__ F, const float* __restrict__ Hm,
                      const float* __restrict__ W1, const float* __restrict__ b1,
                      float* __restrict__ prior, float* __restrict__ post,
                      float* __restrict__ dm1y, float* __restrict__ out_t,
                      __half* __restrict__ a1) {
    __shared__ float feat[64][9];
    int tid = threadIdx.x;
    int b0 = blockIdx.x * 64;
    // ---- phase 1: posterior, 64 rows x 8-lane teams (512 threads) ----
    {
        int lane = tid & 7;
        int b = b0 + (tid >> 3);
        float kg[8];
        #pragma unroll
        for (int o = 0; o < 8; o++) kg[o] = 0.f;
        const float* arow = a2 + (size_t)b * H2;
        for (int k = lane; k < H2; k += 8) {
            float a = arow[k];
            float4 w0 = *(const float4*)(W3 + k*8);
            float4 w1 = *(const float4*)(W3 + k*8 + 4);
            kg[0] = fmaf(a, w0.x, kg[0]); kg[1] = fmaf(a, w0.y, kg[1]);
            kg[2] = fmaf(a, w0.z, kg[2]); kg[3] = fmaf(a, w0.w, kg[3]);
            kg[4] = fmaf(a, w1.x, kg[4]); kg[5] = fmaf(a, w1.y, kg[5]);
            kg[6] = fmaf(a, w1.z, kg[6]); kg[7] = fmaf(a, w1.w, kg[7]);
        }
        #pragma unroll
        for (int off = 4; off > 0; off >>= 1)
            #pragma unroll
            for (int o = 0; o < 8; o++)
                kg[o] += __shfl_down_sync(0xFFFFFFFFu, kg[o], off, 8);
        if (lane == 0) {
            float dy0 = dm1y[b*2+0], dy1 = dm1y[b*2+1];
            #pragma unroll
            for (int m = 0; m < 4; m++) {
                float k0 = kg[2*m]   + __ldg(&b3[2*m]);
                float k1 = kg[2*m+1] + __ldg(&b3[2*m+1]);
                float pv = prior[b*4+m] + k0*dy0 + k1*dy1;
                post[b*4+m]  = pv;
                out_t[b*4+m] = pv;
            }
        }
    }
    __syncthreads();
    // ---- phase 2: features + a1 for next step (512 threads) ----
    feat_a1_body<512>(y_next, F, Hm, W1, b1, post, prior, dm1y, a1, feat, tid, b0);
}

// GRU gate combine, float2-vectorized (HID=200 -> 100 pairs per row)
__global__ void gru_gate_kernel(const float* __restrict__ Gx, const float* __restrict__ Gh,
                                const float* __restrict__ h_in, float* __restrict__ h_out,
                                __half* __restrict__ hnh) {
    int idx = blockIdx.x * blockDim.x + threadIdx.x;     // pair index
    if (idx >= BATCH * HID / 2) return;
    int b = idx / (HID / 2), jp = idx % (HID / 2);
    const float* gx = Gx + (size_t)b * 3 * HID;
    const float* gh = Gh + (size_t)b * 3 * HID;
    int j = jp * 2;
    float2 xz = *(const float2*)&gx[j];
    float2 hz = *(const float2*)&gh[j];
    float2 xr = *(const float2*)&gx[j + HID];
    float2 hr = *(const float2*)&gh[j + HID];
    float2 xh = *(const float2*)&gx[j + 2*HID];
    float2 hh = *(const float2*)&gh[j + 2*HID];
    float2 h  = *(const float2*)&h_in[(size_t)b * HID + j];
    float z0 = 1.f / (1.f + __expf(-(xz.x + hz.x)));
    float z1 = 1.f / (1.f + __expf(-(xz.y + hz.y)));
    float r0 = 1.f / (1.f + __expf(-(xr.x + hr.x)));
    float r1 = 1.f / (1.f + __expf(-(xr.y + hr.y)));
    float c0 = tanhf(xh.x + r0 * hh.x);
    float c1 = tanhf(xh.y + r1 * hh.y);
    float v0 = z0 * h.x + (1.f - z0) * c0;
    float v1 = z1 * h.y + (1.f - z1) * c1;
    *(float2*)&h_out[(size_t)b * HID + j] = make_float2(v0, v1);
    __half2 hv; hv.x = __float2half_rn(v0); hv.y = __float2half_rn(v1);
    *(__half2*)&hnh[(size_t)b * HID + j] = hv;
}

__global__ void out_kernel(const float* __restrict__ a2, const float* __restrict__ W3,
                           const float* __restrict__ b3, const float* __restrict__ dm1y,
                           const float* __restrict__ prior, float* __restrict__ post,
                           float* __restrict__ out_t) {
    int tid = threadIdx.x;
    int lane = tid & 7;
    int b = blockIdx.x * 32 + (tid >> 3);
    float kg[8];
    #pragma unroll
    for (int o = 0; o < 8; o++) kg[o] = 0.f;
    const float* arow = a2 + (size_t)b * H2;
    for (int k = lane; k < H2; k += 8) {
        float a = arow[k];
        float4 w0 = *(const float4*)(W3 + k*8);
        float4 w1 = *(const float4*)(W3 + k*8 + 4);
        kg[0] = fmaf(a, w0.x, kg[0]); kg[1] = fmaf(a, w0.y, kg[1]);
        kg[2] = fmaf(a, w0.z, kg[2]); kg[3] = fmaf(a, w0.w, kg[3]);
        kg[4] = fmaf(a, w1.x, kg[4]); kg[5] = fmaf(a, w1.y, kg[5]);
        kg[6] = fmaf(a, w1.z, kg[6]); kg[7] = fmaf(a, w1.w, kg[7]);
    }
    #pragma unroll
    for (int off = 4; off > 0; off >>= 1)
        #pragma unroll
        for (int o = 0; o < 8; o++)
            kg[o] += __shfl_down_sync(0xFFFFFFFFu, kg[o], off, 8);
    if (lane == 0) {
        float dy0 = dm1y[b*2+0], dy1 = dm1y[b*2+1];
        #pragma unroll
        for (int m = 0; m < 4; m++) {
            float k0 = kg[2*m]   + __ldg(&b3[2*m]);
            float k1 = kg[2*m+1] + __ldg(&b3[2*m+1]);
            float pv = prior[b*4+m] + k0*dy0 + k1*dy1;
            post[b*4+m] = pv;
            out_t[b*4+m] = pv;
        }
    }
}

// ---------------- launch ----------------------------------------------------
extern "C" void kernel_launch(void* const* d_in, const int* in_sizes, int n_in,
                              void* d_out, int out_size) {
    const float* y   = (const float*)d_in[0];
    const float* F   = (const float*)d_in[1];
    const float* Hm  = (const float*)d_in[2];
    const float* W1  = (const float*)d_in[3];
    const float* b1  = (const float*)d_in[4];
    const float* Wg  = (const float*)d_in[5];   // [480,600]
    const float* Ug  = (const float*)d_in[6];   // [200,600]
    const float* bg  = (const float*)d_in[7];   // [2,600]
    const float* W2  = (const float*)d_in[8];   // [200,320]
    const float* b2  = (const float*)d_in[9];
    const float* W3  = (const float*)d_in[10];
    const float* b3  = (const float*)d_in[11];
    const float* hn0 = (const float*)d_in[12];
    float* out = (float*)d_out;

    float *gx, *gh, *a2, *hn, *prior, *post, *dm1y;
    __half *a1, *hnh, *WgTh, *WgTl, *UgTh, *UgTl, *W2Th, *W2Tl;
    cudaGetSymbolAddress((void**)&gx,   g_gx);
    cudaGetSymbolAddress((void**)&gh,   g_gh);
    cudaGetSymbolAddress((void**)&a2,   g_a2);
    cudaGetSymbolAddress((void**)&hn,   g_hn);
    cudaGetSymbolAddress((void**)&prior,g_prior);
    cudaGetSymbolAddress((void**)&post, g_post);
    cudaGetSymbolAddress((void**)&dm1y, g_dm1y);
    cudaGetSymbolAddress((void**)&a1,   g_a1);
    cudaGetSymbolAddress((void**)&hnh,  g_hnh);
    cudaGetSymbolAddress((void**)&WgTh, g_WgTh);
    cudaGetSymbolAddress((void**)&WgTl, g_WgTl);
    cudaGetSymbolAddress((void**)&UgTh, g_UgTh);
    cudaGetSymbolAddress((void**)&UgTl, g_UgTl);
    cudaGetSymbolAddress((void**)&W2Th, g_W2Th);
    cudaGetSymbolAddress((void**)&W2Tl, g_W2Tl);

    const int SMEM8 = 2 * (A_PL + 2 * 128 * ROWB);   // 110592 (NF=8)
    const int SMEM4 = 2 * (A_PL + 2 * 64 * ROWB);    // 73728  (NF=4)
    cudaFuncSetAttribute(gemm_dual,
                         cudaFuncAttributeMaxDynamicSharedMemorySize, SMEM8);
    cudaFuncSetAttribute(gemm_single_relu,
                         cudaFuncAttributeMaxDynamicSharedMemorySize, SMEM4);

    wsplit_kernel<<<(H1*3*HID + 255)/256, 256>>>(Wg, WgTh, WgTl, H1, 3*HID);
    wsplit_kernel<<<(HID*3*HID + 255)/256, 256>>>(Ug, UgTh, UgTl, HID, 3*HID);
    wsplit_kernel<<<(HID*H2 + 255)/256, 256>>>(W2, W2Th, W2Tl, HID, H2);
    init_kernel<<<(BATCH*HID + 255)/256, 256>>>(hn0, hn, hnh, prior, post);

    feat_a1_kernel<<<BATCH/64, 256>>>(y, F, Hm, W1, b1, post, prior, dm1y, a1);

    for (int t = 0; t < T_STEPS; t++) {
        const float* hin = hn + (size_t)(t & 1) * BATCH * HID;
        float* hout      = hn + (size_t)((t + 1) & 1) * BATCH * HID;

        gemm_dual<<<dim3(5, 2 * (BATCH/128)), 256, SMEM8>>>(
            a1,  WgTh, WgTl, bg,         gx,
            hnh, UgTh, UgTl, bg + 3*HID, gh);

        gru_gate_kernel<<<(BATCH*HID/2 + 255)/256, 256>>>(gx, gh, hin, hout, hnh);

        gemm_single_relu<<<dim3(5, BATCH/128), 256, SMEM4>>>(
            hnh, W2Th, W2Tl, b2, a2, H2);

        if (t + 1 < T_STEPS) {
            post_feat_kernel<<<BATCH/64, 512>>>(a2, W3, b3,
                y + (size_t)(t + 1) * BATCH * NDIM, F, Hm, W1, b1,
                prior, post, dm1y, out + (size_t)t * BATCH * MDIM, a1);
        } else {
            out_kernel<<<BATCH/32, 256>>>(a2, W3, b3, dm1y, prior, post,
                                          out + (size_t)t * BATCH * MDIM);
        }
    }
}